// round 10
// baseline (speedup 1.0000x reference)
#include <cuda_runtime.h>
#include <cuda_bf16.h>
#include <cstdint>

#define NN 100000
#define NE 800000
#define HD 256
#define KE 259      // H + 3 edge features
#define NL 6
#define NGT 29      // gate types

// ---------------- scratch (static device globals) ----------------
static __device__ __align__(16) __nv_bfloat16 g_ahi[(size_t)NN * HD];
static __device__ __align__(16) __nv_bfloat16 g_alo[(size_t)NN * HD];
static __device__ __align__(16) __nv_bfloat16 g_bhi[(size_t)NN * HD];
static __device__ __align__(16) __nv_bfloat16 g_blo[(size_t)NN * HD];
static __device__ __align__(16) __nv_bfloat16 g_nhi[(size_t)NN * HD];
static __device__ __align__(16) __nv_bfloat16 g_nlo[(size_t)NN * HD];
static __device__ float g_z[(size_t)NN * HD];
static __device__ float g_P[(size_t)NN * HD];
#define W1SZ (NL * HD * HD)
#define W2SZ (NL * HD * 512)
#define WHSZ (HD * HD)
#define EMBSZ (NGT * HD)
static __device__ __align__(16) __nv_bfloat16 g_w1hi[W1SZ], g_w1lo[W1SZ];
static __device__ __align__(16) __nv_bfloat16 g_w2hi[W2SZ], g_w2lo[W2SZ];
static __device__ __align__(16) __nv_bfloat16 g_whhi[WHSZ], g_whlo[WHSZ];
static __device__ __align__(16) __nv_bfloat16 g_ehi[EMBSZ], g_elo[EMBSZ];
static __device__ float g_zem[EMBSZ];
static __device__ float g_t2[EMBSZ];

static __device__ float g_inv[NN];
static __device__ int   g_deg[NN];
static __device__ int   g_rowptr[NN + 1];
static __device__ int   g_cursor[NN];
static __device__ int   g_esorted[NE];

// ---------------- preprocessing: deterministic CSR by dst ----------------
__global__ void k_deg(const int* __restrict__ dst, int e) {
    int i = blockIdx.x * blockDim.x + threadIdx.x;
    if (i < e) atomicAdd(&g_deg[dst[i]], 1);
}

__global__ void k_scan(int n) {
    __shared__ int s[1024];
    int t = threadIdx.x;
    int per = (n + 1023) / 1024;
    int lo = t * per;
    int hi = lo + per; if (hi > n) hi = n;
    int sum = 0;
    for (int i = lo; i < hi; i++) sum += g_deg[i];
    s[t] = sum;
    __syncthreads();
    for (int off = 1; off < 1024; off <<= 1) {
        int v = (t >= off) ? s[t - off] : 0;
        __syncthreads();
        s[t] += v;
        __syncthreads();
    }
    int run = s[t] - sum;
    for (int i = lo; i < hi; i++) {
        g_rowptr[i] = run;
        g_cursor[i] = run;
        run += g_deg[i];
    }
    if (t == 1023) g_rowptr[n] = s[1023];
}

__global__ void k_scatter(const int* __restrict__ dst, int e) {
    int i = blockIdx.x * blockDim.x + threadIdx.x;
    if (i < e) {
        int d = dst[i];
        int pos = atomicAdd(&g_cursor[d], 1);
        g_esorted[pos] = i;
    }
}

__global__ void k_segsort(int n) {
    int v = blockIdx.x * blockDim.x + threadIdx.x;
    if (v >= n) return;
    int lo = g_rowptr[v], hi = g_rowptr[v + 1];
    for (int i = lo + 1; i < hi; i++) {
        int key = g_esorted[i];
        int j = i - 1;
        while (j >= lo && g_esorted[j] > key) { g_esorted[j + 1] = g_esorted[j]; j--; }
        g_esorted[j + 1] = key;
    }
}

// ---------------- weight + emb pre-split ----------------
__global__ void k_wsplit(const float* __restrict__ W1, const float* __restrict__ W2,
                         const float* __restrict__ Wh1, const float* __restrict__ emb) {
    int i = blockIdx.x * blockDim.x + threadIdx.x;
    float v; __nv_bfloat16* dh; __nv_bfloat16* dl; int o;
    if (i < W1SZ) {
        int l = i / (HD * HD), rem = i % (HD * HD);
        int row = rem / HD, col = rem % HD;
        v = W1[(size_t)l * HD * KE + (size_t)row * KE + col];
        dh = g_w1hi; dl = g_w1lo; o = i;
    } else if (i < W1SZ + W2SZ) {
        o = i - W1SZ;
        v = W2[o];
        dh = g_w2hi; dl = g_w2lo;
    } else if (i < W1SZ + W2SZ + WHSZ) {
        o = i - W1SZ - W2SZ;
        v = Wh1[o];
        dh = g_whhi; dl = g_whlo;
    } else if (i < W1SZ + W2SZ + WHSZ + EMBSZ) {
        o = i - W1SZ - W2SZ - WHSZ;
        v = emb[o];
        dh = g_ehi; dl = g_elo;
    } else return;
    __nv_bfloat16 h = __float2bfloat16_rn(v);
    dh[o] = h;
    dl[o] = __float2bfloat16_rn(v - __bfloat162float(h));
}

// ---------------- init: h0 = emb[gate] (bf16 hi/lo), inv_deg ----------------
__global__ void k_init(const int* __restrict__ gate, const float* __restrict__ emb, int n) {
    int idx = blockIdx.x * blockDim.x + threadIdx.x;
    if (idx >= n * HD) return;
    int v = idx / HD, f = idx % HD;
    float x = emb[gate[v] * HD + f];
    __nv_bfloat16 h = __float2bfloat16_rn(x);
    g_ahi[idx] = h;
    g_alo[idx] = __float2bfloat16_rn(x - __bfloat162float(h));
    if (f == 0) g_inv[v] = 1.0f / fmaxf((float)g_deg[v], 1.0f);
}

// ---------------- layer-0 gather: z0 / P0 from 29-type tables ----------------
__global__ void k_gather0(const int* __restrict__ gate, int n) {
    int idx = blockIdx.x * blockDim.x + threadIdx.x;
    if (idx >= n * HD) return;
    int v = idx / HD, f = idx % HD;
    int g = gate[v];
    g_z[idx] = g_zem[g * HD + f];
    g_P[idx] = g_t2[g * HD + f];
}

// ---------------- warp-MMA helpers ----------------
__device__ __forceinline__ uint32_t s2u(const void* p) {
    return (uint32_t)__cvta_generic_to_shared(p);
}
__device__ __forceinline__ void ldsm4(uint32_t* r, uint32_t addr) {
    asm volatile("ldmatrix.sync.aligned.m8n8.x4.shared.b16 {%0,%1,%2,%3}, [%4];"
        : "=r"(r[0]), "=r"(r[1]), "=r"(r[2]), "=r"(r[3]) : "r"(addr));
}
__device__ __forceinline__ void mma16816(float* d, const uint32_t* a, const uint32_t* b) {
    asm volatile("mma.sync.aligned.m16n8k16.row.col.f32.bf16.bf16.f32 "
        "{%0,%1,%2,%3}, {%4,%5,%6,%7}, {%8,%9}, {%0,%1,%2,%3};"
        : "+f"(d[0]), "+f"(d[1]), "+f"(d[2]), "+f"(d[3])
        : "r"(a[0]), "r"(a[1]), "r"(a[2]), "r"(a[3]), "r"(b[0]), "r"(b[1]));
}
__device__ __forceinline__ void cpa16(uint32_t d, const void* s) {
    asm volatile("cp.async.ca.shared.global [%0], [%1], 16;" :: "r"(d), "l"(s));
}
#define CP_COMMIT() asm volatile("cp.async.commit_group;" ::: "memory")

// ---------------- bf16x3 MMA GEMM, 512 threads, BK=64, double-buffered ----------------
#define PITCH 72
#define TSZ   18432
#define STG   73728
__global__ __launch_bounds__(512) void k_gemm_mma(
    const __nv_bfloat16* __restrict__ A0h, const __nv_bfloat16* __restrict__ A0l,
    const __nv_bfloat16* __restrict__ A1h, const __nv_bfloat16* __restrict__ A1l,
    const __nv_bfloat16* __restrict__ Bh,  const __nv_bfloat16* __restrict__ Bl,
    const float* __restrict__ bias, const float* __restrict__ Padd,
    float* __restrict__ outf, __nv_bfloat16* __restrict__ outhi, __nv_bfloat16* __restrict__ outlo,
    int K, int ws, int M, int act)
{
    extern __shared__ char smem[];
    const uint32_t us = s2u(smem);

    const int tid  = threadIdx.x;
    const int lane = tid & 31;
    const int wid  = tid >> 5;
    const int r0   = blockIdx.x * 128;
    const int nb0  = blockIdx.y * 128;
    const int m0w  = (wid >> 2) * 32;
    const int n0w  = (wid & 3) * 32;

    float acc[2][4][4];
#pragma unroll
    for (int i = 0; i < 2; i++)
#pragma unroll
        for (int j = 0; j < 4; j++)
#pragma unroll
            for (int t = 0; t < 4; t++) acc[i][j][t] = 0.f;

    const int nch = K >> 6;
    const int lr  = tid >> 2;
    const int lcb = (tid & 3) * 8;

    auto load_chunk = [&](int ch, int stage) {
        const int kc = ch << 6;
        const __nv_bfloat16* Ah = (kc < HD) ? A0h : A1h;
        const __nv_bfloat16* Al = (kc < HD) ? A0l : A1l;
        const int acol = (kc < HD) ? kc : (kc - HD);
        const uint32_t base = us + stage * STG;
        int g = r0 + lr; if (g >= M) g = M - 1;
#pragma unroll
        for (int gi = 0; gi < 2; gi++) {
            int c = lcb + gi * 32;
            uint32_t so = (uint32_t)(lr * PITCH + c) * 2;
            cpa16(base + so,           &Ah[(size_t)g * HD + acol + c]);
            cpa16(base + TSZ + so,     &Al[(size_t)g * HD + acol + c]);
            cpa16(base + 2 * TSZ + so, &Bh[(size_t)(nb0 + lr) * ws + kc + c]);
            cpa16(base + 3 * TSZ + so, &Bl[(size_t)(nb0 + lr) * ws + kc + c]);
        }
    };

    load_chunk(0, 0);
    CP_COMMIT();

    for (int ch = 0; ch < nch; ch++) {
        if (ch + 1 < nch) {
            load_chunk(ch + 1, (ch + 1) & 1);
            CP_COMMIT();
            asm volatile("cp.async.wait_group 1;" ::: "memory");
        } else {
            asm volatile("cp.async.wait_group 0;" ::: "memory");
        }
        __syncthreads();

        const uint32_t base = us + (ch & 1) * STG;
        const uint32_t uA = base, uAl = base + TSZ, uB = base + 2 * TSZ, uBl = base + 3 * TSZ;
#pragma unroll
        for (int ks = 0; ks < 4; ks++) {
            const int kk = ks * 16;
            uint32_t ah[2][4], al[2][4];
            {
                int ar = (lane & 7) + ((lane >> 3) & 1) * 8;
                int ac = kk + ((lane >> 4) & 1) * 8;
#pragma unroll
                for (int mf = 0; mf < 2; mf++) {
                    uint32_t off = (uint32_t)((m0w + mf * 16 + ar) * PITCH + ac) * 2;
                    ldsm4(ah[mf], uA + off);
                    ldsm4(al[mf], uAl + off);
                }
            }
            uint32_t bh[2][4], bl[2][4];
            {
                int br = ((lane >> 4) & 1) * 8 + (lane & 7);
                int bc = kk + ((lane >> 3) & 1) * 8;
#pragma unroll
                for (int nb2 = 0; nb2 < 2; nb2++) {
                    uint32_t off = (uint32_t)((n0w + nb2 * 16 + br) * PITCH + bc) * 2;
                    ldsm4(bh[nb2], uB + off);
                    ldsm4(bl[nb2], uBl + off);
                }
            }
#pragma unroll
            for (int mf = 0; mf < 2; mf++)
#pragma unroll
                for (int nf = 0; nf < 4; nf++) {
                    const uint32_t* B0 = &bh[nf >> 1][(nf & 1) * 2];
                    const uint32_t* B1 = &bl[nf >> 1][(nf & 1) * 2];
                    mma16816(acc[mf][nf], ah[mf], B0);
                    mma16816(acc[mf][nf], al[mf], B0);
                    mma16816(acc[mf][nf], ah[mf], B1);
                }
        }
        __syncthreads();
    }

    // epilogue
    const int rq = lane >> 2, cq = (lane & 3) * 2;
#pragma unroll
    for (int mf = 0; mf < 2; mf++) {
#pragma unroll
        for (int nf = 0; nf < 4; nf++) {
            int col = nb0 + n0w + nf * 8 + cq;
            float b0 = 0.f, b1 = 0.f;
            if (bias) { b0 = __ldg(&bias[col]); b1 = __ldg(&bias[col + 1]); }
            int row0 = r0 + m0w + mf * 16 + rq;
#pragma unroll
            for (int half = 0; half < 2; half++) {
                int row = row0 + half * 8;
                if (row < M) {
                    size_t idx = (size_t)row * HD + col;
                    float ox = acc[mf][nf][half * 2 + 0];
                    float oy = acc[mf][nf][half * 2 + 1];
                    if (Padd) { ox += __ldg(&Padd[idx]); oy += __ldg(&Padd[idx + 1]); }
                    ox += b0; oy += b1;
                    if (act) { ox = fmaxf(ox, 0.f); oy = fmaxf(oy, 0.f); }
                    if (outf) *(float2*)&outf[idx] = make_float2(ox, oy);
                    if (outhi) {
                        __nv_bfloat16 h0 = __float2bfloat16_rn(ox);
                        __nv_bfloat16 h1 = __float2bfloat16_rn(oy);
                        *(__nv_bfloat162*)&outhi[idx] = {h0, h1};
                        *(__nv_bfloat162*)&outlo[idx] =
                            {__float2bfloat16_rn(ox - __bfloat162float(h0)),
                             __float2bfloat16_rn(oy - __bfloat162float(h1))};
                    }
                }
            }
        }
    }
}

// ---------------- fused edge + segmented mean: warp-per-node, 2-edge pipelined ----------------
#define ESEG_BLOCKS 1563
__global__ __launch_bounds__(256) void k_edge_seg(
    const float* __restrict__ z, const int* __restrict__ src,
    const float* __restrict__ w, const float* __restrict__ W1l, int n)
{
    __shared__ float sc[3][HD];
    const int tid  = threadIdx.x;
    const int lane = tid & 31;
    const int wloc = tid >> 5;

    if (tid < HD) {
        sc[0][tid] = W1l[(size_t)tid * KE + HD + 0];
        sc[1][tid] = W1l[(size_t)tid * KE + HD + 1];
        sc[2][tid] = W1l[(size_t)tid * KE + HD + 2];
    }
    __syncthreads();

    const int f0 = lane * 8;
    float c0[8], c1[8], c2[8];
#pragma unroll
    for (int j = 0; j < 8; j++) {
        c0[j] = sc[0][f0 + j];
        c1[j] = sc[1][f0 + j];
        c2[j] = sc[2][f0 + j];
    }

    const int gwarp  = blockIdx.x * 8 + wloc;
    const int nwarps = ESEG_BLOCKS * 8;

    for (int v = gwarp; v < n; v += nwarps) {
        const int lo = g_rowptr[v], hi = g_rowptr[v + 1];
        float a[8];
#pragma unroll
        for (int j = 0; j < 8; j++) a[j] = 0.f;

        int i = lo;
        for (; i + 2 <= hi; i += 2) {
            int e0 = __ldg(&g_esorted[i]);
            int e1 = __ldg(&g_esorted[i + 1]);
            int s0 = __ldg(&src[e0]);
            int s1 = __ldg(&src[e1]);
            float w00 = __ldg(&w[(size_t)e0 * 3 + 0]);
            float w01 = __ldg(&w[(size_t)e0 * 3 + 1]);
            float w02 = __ldg(&w[(size_t)e0 * 3 + 2]);
            float w10 = __ldg(&w[(size_t)e1 * 3 + 0]);
            float w11 = __ldg(&w[(size_t)e1 * 3 + 1]);
            float w12 = __ldg(&w[(size_t)e1 * 3 + 2]);
            const float4* zr0 = (const float4*)&z[(size_t)s0 * HD];
            const float4* zr1 = (const float4*)&z[(size_t)s1 * HD];
            float4 za0 = __ldg(&zr0[lane * 2 + 0]);
            float4 zb0 = __ldg(&zr0[lane * 2 + 1]);
            float4 za1 = __ldg(&zr1[lane * 2 + 0]);
            float4 zb1 = __ldg(&zr1[lane * 2 + 1]);
            float t0[8] = {za0.x, za0.y, za0.z, za0.w, zb0.x, zb0.y, zb0.z, zb0.w};
            float t1[8] = {za1.x, za1.y, za1.z, za1.w, zb1.x, zb1.y, zb1.z, zb1.w};
#pragma unroll
            for (int j = 0; j < 8; j++) {
                float v0 = t0[j] + c0[j] * w00 + c1[j] * w01 + c2[j] * w02;
                a[j] += (v0 > 0.f) ? v0 : 0.01f * v0;
            }
#pragma unroll
            for (int j = 0; j < 8; j++) {
                float v1 = t1[j] + c0[j] * w10 + c1[j] * w11 + c2[j] * w12;
                a[j] += (v1 > 0.f) ? v1 : 0.01f * v1;
            }
        }
        if (i < hi) {
            int e = __ldg(&g_esorted[i]);
            int s = __ldg(&src[e]);
            float w0 = __ldg(&w[(size_t)e * 3 + 0]);
            float w1 = __ldg(&w[(size_t)e * 3 + 1]);
            float w2 = __ldg(&w[(size_t)e * 3 + 2]);
            const float4* zr = (const float4*)&z[(size_t)s * HD];
            float4 za = __ldg(&zr[lane * 2 + 0]);
            float4 zb = __ldg(&zr[lane * 2 + 1]);
            float t[8] = {za.x, za.y, za.z, za.w, zb.x, zb.y, zb.z, zb.w};
#pragma unroll
            for (int j = 0; j < 8; j++) {
                float val = t[j] + c0[j] * w0 + c1[j] * w1 + c2[j] * w2;
                a[j] += (val > 0.f) ? val : 0.01f * val;
            }
        }
        const float inv = g_inv[v];
        uint32_t hpack[4], lpack[4];
#pragma unroll
        for (int j = 0; j < 4; j++) {
            float r0v = a[j * 2 + 0] * inv;
            float r1v = a[j * 2 + 1] * inv;
            __nv_bfloat16 h0 = __float2bfloat16_rn(r0v);
            __nv_bfloat16 h1 = __float2bfloat16_rn(r1v);
            __nv_bfloat162 hp = {h0, h1};
            __nv_bfloat162 lp = {__float2bfloat16_rn(r0v - __bfloat162float(h0)),
                                 __float2bfloat16_rn(r1v - __bfloat162float(h1))};
            hpack[j] = *(uint32_t*)&hp;
            lpack[j] = *(uint32_t*)&lp;
        }
        size_t idx = (size_t)v * HD + f0;
        *(uint4*)&g_nhi[idx] = *(uint4*)hpack;
        *(uint4*)&g_nlo[idx] = *(uint4*)lpack;
    }
}

// ---------------- head ----------------
__global__ void k_head2(const float* __restrict__ x, const float* __restrict__ Wh2,
                        const float* __restrict__ bh2, float* __restrict__ out, int n) {
    int gtid = blockIdx.x * blockDim.x + threadIdx.x;
    int v = gtid >> 5;
    int lane = gtid & 31;
    if (v >= n) return;
    float s = 0.f;
#pragma unroll
    for (int k = lane; k < HD; k += 32) s += x[(size_t)v * HD + k] * Wh2[k];
#pragma unroll
    for (int o = 16; o; o >>= 1) s += __shfl_xor_sync(0xffffffffu, s, o);
    if (lane == 0) out[v] = s + bh2[0];
}

// ---------------- host ----------------
extern "C" void kernel_launch(void* const* d_in, const int* in_sizes, int n_in,
                              void* d_out, int out_size) {
    const int*   gate = (const int*)  d_in[0];
    const int*   src  = (const int*)  d_in[1];
    const int*   dst  = (const int*)  d_in[2];
    const float* w    = (const float*)d_in[3];
    const float* emb  = (const float*)d_in[4];
    const float* W1   = (const float*)d_in[5];
    const float* W2   = (const float*)d_in[6];
    const float* b2   = (const float*)d_in[7];
    const float* Wh1  = (const float*)d_in[8];
    const float* bh1  = (const float*)d_in[9];
    const float* Wh2  = (const float*)d_in[10];
    const float* bh2  = (const float*)d_in[11];
    float* out = (float*)d_out;

    int n = in_sizes[0];
    int e = in_sizes[1];

    static cudaStream_t s2 = nullptr;
    static cudaEvent_t evA = nullptr, evB = nullptr;
    if (!s2) {   // first call is the uncaptured correctness run
        cudaFuncSetAttribute(k_gemm_mma, cudaFuncAttributeMaxDynamicSharedMemorySize, 2 * STG);
        cudaStreamCreateWithFlags(&s2, cudaStreamNonBlocking);
        cudaEventCreateWithFlags(&evA, cudaEventDisableTiming);
        cudaEventCreateWithFlags(&evB, cudaEventDisableTiming);
    }

    void* p;
    cudaGetSymbolAddress(&p, g_ahi); __nv_bfloat16* ahi = (__nv_bfloat16*)p;
    cudaGetSymbolAddress(&p, g_alo); __nv_bfloat16* alo = (__nv_bfloat16*)p;
    cudaGetSymbolAddress(&p, g_bhi); __nv_bfloat16* bhi = (__nv_bfloat16*)p;
    cudaGetSymbolAddress(&p, g_blo); __nv_bfloat16* blo = (__nv_bfloat16*)p;
    cudaGetSymbolAddress(&p, g_nhi); __nv_bfloat16* nhi = (__nv_bfloat16*)p;
    cudaGetSymbolAddress(&p, g_nlo); __nv_bfloat16* nlo = (__nv_bfloat16*)p;
    cudaGetSymbolAddress(&p, g_z);   float* z = (float*)p;
    cudaGetSymbolAddress(&p, g_P);   float* P = (float*)p;
    cudaGetSymbolAddress(&p, g_zem); float* zem = (float*)p;
    cudaGetSymbolAddress(&p, g_t2);  float* t2 = (float*)p;
    cudaGetSymbolAddress(&p, g_w1hi); __nv_bfloat16* w1hi = (__nv_bfloat16*)p;
    cudaGetSymbolAddress(&p, g_w1lo); __nv_bfloat16* w1lo = (__nv_bfloat16*)p;
    cudaGetSymbolAddress(&p, g_w2hi); __nv_bfloat16* w2hi = (__nv_bfloat16*)p;
    cudaGetSymbolAddress(&p, g_w2lo); __nv_bfloat16* w2lo = (__nv_bfloat16*)p;
    cudaGetSymbolAddress(&p, g_whhi); __nv_bfloat16* whhi = (__nv_bfloat16*)p;
    cudaGetSymbolAddress(&p, g_whlo); __nv_bfloat16* whlo = (__nv_bfloat16*)p;
    cudaGetSymbolAddress(&p, g_ehi); __nv_bfloat16* ehi = (__nv_bfloat16*)p;
    cudaGetSymbolAddress(&p, g_elo); __nv_bfloat16* elo = (__nv_bfloat16*)p;
    cudaGetSymbolAddress(&p, g_deg); int* degp = (int*)p;

    cudaMemsetAsync(degp, 0, (size_t)n * sizeof(int));
    k_deg    <<<(e + 255) / 256, 256>>>(dst, e);
    k_scan   <<<1, 1024>>>(n);
    k_scatter<<<(e + 255) / 256, 256>>>(dst, e);
    k_segsort<<<(n + 255) / 256, 256>>>(n);
    k_wsplit <<<(W1SZ + W2SZ + WHSZ + EMBSZ + 255) / 256, 256>>>(W1, W2, Wh1, emb);
    k_init   <<<((size_t)n * HD + 255) / 256, 256>>>(gate, emb, n);

    __nv_bfloat16 *pah = ahi, *pal = alo, *pbh = bhi, *pbl = blo;
    dim3 gg((n + 127) / 128, 2);
    dim3 gt(1, 2);

    // layer 0: 29-type tables instead of full GEMMs
    k_gemm_mma<<<gt, 512, 2 * STG>>>(ehi, elo, ehi, elo, w1hi, w1lo,
                                     nullptr, nullptr, zem, nullptr, nullptr,
                                     HD, HD, NGT, 0);
    k_gemm_mma<<<gt, 512, 2 * STG>>>(ehi, elo, ehi, elo, w2hi, w2lo,
                                     nullptr, nullptr, t2, nullptr, nullptr,
                                     HD, 512, NGT, 0);
    k_gather0<<<((size_t)n * HD + 255) / 256, 256>>>(gate, n);

    for (int l = 0; l < NL; l++) {
        const float* W1l = W1 + (size_t)l * HD * KE;
        if (l > 0) {
            // z = h @ W1h^T
            k_gemm_mma<<<gg, 512, 2 * STG>>>(pah, pal, pah, pal,
                                             w1hi + (size_t)l * HD * HD, w1lo + (size_t)l * HD * HD,
                                             nullptr, nullptr, z, nullptr, nullptr, HD, HD, n, 0);
            // fork: P = h @ W2a^T on s2, concurrent with edge_seg
            cudaEventRecord(evA, 0);
            cudaStreamWaitEvent(s2, evA, 0);
            k_gemm_mma<<<gg, 512, 2 * STG, s2>>>(pah, pal, pah, pal,
                                                 w2hi + (size_t)l * HD * 512, w2lo + (size_t)l * HD * 512,
                                                 nullptr, nullptr, P, nullptr, nullptr, HD, 512, n, 0);
            k_edge_seg<<<ESEG_BLOCKS, 256>>>(z, src, w, W1l, n);
            cudaEventRecord(evB, s2);
            cudaStreamWaitEvent(0, evB, 0);
        } else {
            k_edge_seg<<<ESEG_BLOCKS, 256>>>(z, src, w, W1l, n);
        }
        // h' = relu(hN @ W2b^T + P + b2)
        k_gemm_mma<<<gg, 512, 2 * STG>>>(nhi, nlo, nhi, nlo,
                                         w2hi + (size_t)l * HD * 512 + 256,
                                         w2lo + (size_t)l * HD * 512 + 256,
                                         b2 + (size_t)l * HD, P, nullptr, pbh, pbl, HD, 512, n, 1);
        __nv_bfloat16* t;
        t = pah; pah = pbh; pbh = t;
        t = pal; pal = pbl; pbl = t;
    }
    k_gemm_mma<<<gg, 512, 2 * STG>>>(pah, pal, pah, pal, whhi, whlo,
                                     bh1, nullptr, z, nullptr, nullptr, HD, HD, n, 1);
    k_head2<<<((size_t)n * 32 + 255) / 256, 256>>>(z, Wh2, bh2, out, n);
}

// round 12
// speedup vs baseline: 1.0853x; 1.0853x over previous
#include <cuda_runtime.h>
#include <cuda_bf16.h>
#include <cstdint>

#define NN 100000
#define NE 800000
#define HD 256
#define KE 259      // H + 3 edge features
#define NL 6
#define NGT 29      // gate types

// ---------------- scratch (static device globals) ----------------
static __device__ __align__(16) __nv_bfloat16 g_ahi[(size_t)NN * HD];
static __device__ __align__(16) __nv_bfloat16 g_alo[(size_t)NN * HD];
static __device__ __align__(16) __nv_bfloat16 g_bhi[(size_t)NN * HD];
static __device__ __align__(16) __nv_bfloat16 g_blo[(size_t)NN * HD];
static __device__ __align__(16) __nv_bfloat16 g_nhi[(size_t)NN * HD];
static __device__ __align__(16) __nv_bfloat16 g_nlo[(size_t)NN * HD];
static __device__ float g_z[(size_t)NN * HD];
#define W1SZ (NL * HD * HD)
#define W2SZ (NL * HD * 512)
#define WHSZ (HD * HD)
#define EMBSZ (NGT * HD)
static __device__ __align__(16) __nv_bfloat16 g_w1hi[W1SZ], g_w1lo[W1SZ];
static __device__ __align__(16) __nv_bfloat16 g_w2hi[W2SZ], g_w2lo[W2SZ];
static __device__ __align__(16) __nv_bfloat16 g_whhi[WHSZ], g_whlo[WHSZ];
static __device__ __align__(16) __nv_bfloat16 g_ehi[EMBSZ], g_elo[EMBSZ];
static __device__ float g_zem[EMBSZ];

static __device__ float g_inv[NN];
static __device__ int   g_deg[NN];
static __device__ int   g_rowptr[NN + 1];
static __device__ int   g_cursor[NN];
static __device__ int   g_esorted[NE];

// ---------------- preprocessing: deterministic CSR by dst ----------------
__global__ void k_zero_deg(int n) {
    int i = blockIdx.x * blockDim.x + threadIdx.x;
    if (i < n) g_deg[i] = 0;
}

__global__ void k_deg(const int* __restrict__ dst, int e) {
    int i = blockIdx.x * blockDim.x + threadIdx.x;
    if (i < e) atomicAdd(&g_deg[dst[i]], 1);
}

__global__ void k_scan(int n) {
    __shared__ int s[1024];
    int t = threadIdx.x;
    int per = (n + 1023) / 1024;
    int lo = t * per;
    int hi = lo + per; if (hi > n) hi = n;
    int sum = 0;
    for (int i = lo; i < hi; i++) sum += g_deg[i];
    s[t] = sum;
    __syncthreads();
    for (int off = 1; off < 1024; off <<= 1) {
        int v = (t >= off) ? s[t - off] : 0;
        __syncthreads();
        s[t] += v;
        __syncthreads();
    }
    int run = s[t] - sum;
    for (int i = lo; i < hi; i++) {
        g_rowptr[i] = run;
        g_cursor[i] = run;
        g_inv[i] = 1.0f / fmaxf((float)g_deg[i], 1.0f);
        run += g_deg[i];
    }
    if (t == 1023) g_rowptr[n] = s[1023];
}

__global__ void k_scatter(const int* __restrict__ dst, int e) {
    int i = blockIdx.x * blockDim.x + threadIdx.x;
    if (i < e) {
        int d = dst[i];
        int pos = atomicAdd(&g_cursor[d], 1);
        g_esorted[pos] = i;
    }
}

__global__ void k_segsort(int n) {
    int v = blockIdx.x * blockDim.x + threadIdx.x;
    if (v >= n) return;
    int lo = g_rowptr[v], hi = g_rowptr[v + 1];
    for (int i = lo + 1; i < hi; i++) {
        int key = g_esorted[i];
        int j = i - 1;
        while (j >= lo && g_esorted[j] > key) { g_esorted[j + 1] = g_esorted[j]; j--; }
        g_esorted[j + 1] = key;
    }
}

// ---------------- weight + emb pre-split ----------------
__global__ void k_wsplit(const float* __restrict__ W1, const float* __restrict__ W2,
                         const float* __restrict__ Wh1, const float* __restrict__ emb) {
    int i = blockIdx.x * blockDim.x + threadIdx.x;
    float v; __nv_bfloat16* dh; __nv_bfloat16* dl; int o;
    if (i < W1SZ) {
        int l = i / (HD * HD), rem = i % (HD * HD);
        int row = rem / HD, col = rem % HD;
        v = W1[(size_t)l * HD * KE + (size_t)row * KE + col];
        dh = g_w1hi; dl = g_w1lo; o = i;
    } else if (i < W1SZ + W2SZ) {
        o = i - W1SZ;
        v = W2[o];
        dh = g_w2hi; dl = g_w2lo;
    } else if (i < W1SZ + W2SZ + WHSZ) {
        o = i - W1SZ - W2SZ;
        v = Wh1[o];
        dh = g_whhi; dl = g_whlo;
    } else if (i < W1SZ + W2SZ + WHSZ + EMBSZ) {
        o = i - W1SZ - W2SZ - WHSZ;
        v = emb[o];
        dh = g_ehi; dl = g_elo;
    } else return;
    __nv_bfloat16 h = __float2bfloat16_rn(v);
    dh[o] = h;
    dl[o] = __float2bfloat16_rn(v - __bfloat162float(h));
}

// ---------------- init: h0 = emb[gate] (bf16 hi/lo) ----------------
__global__ void k_init(const int* __restrict__ gate, const float* __restrict__ emb, int n) {
    int idx = blockIdx.x * blockDim.x + threadIdx.x;
    if (idx >= n * HD) return;
    int v = idx / HD, f = idx % HD;
    float x = emb[gate[v] * HD + f];
    __nv_bfloat16 h = __float2bfloat16_rn(x);
    g_ahi[idx] = h;
    g_alo[idx] = __float2bfloat16_rn(x - __bfloat162float(h));
}

// ---------------- layer-0 gather: z0 = zem[gate] ----------------
__global__ void k_gather0(const int* __restrict__ gate, int n) {
    int idx = blockIdx.x * blockDim.x + threadIdx.x;
    if (idx >= n * HD) return;
    int v = idx / HD, f = idx % HD;
    g_z[idx] = g_zem[gate[v] * HD + f];
}

// ---------------- warp-MMA helpers ----------------
__device__ __forceinline__ uint32_t s2u(const void* p) {
    return (uint32_t)__cvta_generic_to_shared(p);
}
__device__ __forceinline__ void ldsm4(uint32_t* r, uint32_t addr) {
    asm volatile("ldmatrix.sync.aligned.m8n8.x4.shared.b16 {%0,%1,%2,%3}, [%4];"
        : "=r"(r[0]), "=r"(r[1]), "=r"(r[2]), "=r"(r[3]) : "r"(addr));
}
__device__ __forceinline__ void mma16816(float* d, const uint32_t* a, const uint32_t* b) {
    asm volatile("mma.sync.aligned.m16n8k16.row.col.f32.bf16.bf16.f32 "
        "{%0,%1,%2,%3}, {%4,%5,%6,%7}, {%8,%9}, {%0,%1,%2,%3};"
        : "+f"(d[0]), "+f"(d[1]), "+f"(d[2]), "+f"(d[3])
        : "r"(a[0]), "r"(a[1]), "r"(a[2]), "r"(a[3]), "r"(b[0]), "r"(b[1]));
}
__device__ __forceinline__ void cpa16(uint32_t d, const void* s) {
    asm volatile("cp.async.ca.shared.global [%0], [%1], 16;" :: "r"(d), "l"(s));
}
#define CP_COMMIT() asm volatile("cp.async.commit_group;" ::: "memory")

// ---------------- bf16x3 MMA GEMM, 512 threads, BK=64, double-buffered ----------------
#define PITCH 72
#define TSZ   18432
#define STG   73728
__global__ __launch_bounds__(512) void k_gemm_mma(
    const __nv_bfloat16* __restrict__ A0h, const __nv_bfloat16* __restrict__ A0l,
    const __nv_bfloat16* __restrict__ A1h, const __nv_bfloat16* __restrict__ A1l,
    const __nv_bfloat16* __restrict__ Bh,  const __nv_bfloat16* __restrict__ Bl,
    const float* __restrict__ bias,
    float* __restrict__ outf, __nv_bfloat16* __restrict__ outhi, __nv_bfloat16* __restrict__ outlo,
    int K, int ws, int M, int act)
{
    extern __shared__ char smem[];
    const uint32_t us = s2u(smem);

    const int tid  = threadIdx.x;
    const int lane = tid & 31;
    const int wid  = tid >> 5;
    const int r0   = blockIdx.x * 128;
    const int nb0  = blockIdx.y * 128;
    const int m0w  = (wid >> 2) * 32;
    const int n0w  = (wid & 3) * 32;

    float acc[2][4][4];
#pragma unroll
    for (int i = 0; i < 2; i++)
#pragma unroll
        for (int j = 0; j < 4; j++)
#pragma unroll
            for (int t = 0; t < 4; t++) acc[i][j][t] = 0.f;

    const int nch = K >> 6;
    const int lr  = tid >> 2;
    const int lcb = (tid & 3) * 8;

    auto load_chunk = [&](int ch, int stage) {
        const int kc = ch << 6;
        const __nv_bfloat16* Ah = (kc < HD) ? A0h : A1h;
        const __nv_bfloat16* Al = (kc < HD) ? A0l : A1l;
        const int acol = (kc < HD) ? kc : (kc - HD);
        const uint32_t base = us + stage * STG;
        int g = r0 + lr; if (g >= M) g = M - 1;
#pragma unroll
        for (int gi = 0; gi < 2; gi++) {
            int c = lcb + gi * 32;
            uint32_t so = (uint32_t)(lr * PITCH + c) * 2;
            cpa16(base + so,           &Ah[(size_t)g * HD + acol + c]);
            cpa16(base + TSZ + so,     &Al[(size_t)g * HD + acol + c]);
            cpa16(base + 2 * TSZ + so, &Bh[(size_t)(nb0 + lr) * ws + kc + c]);
            cpa16(base + 3 * TSZ + so, &Bl[(size_t)(nb0 + lr) * ws + kc + c]);
        }
    };

    load_chunk(0, 0);
    CP_COMMIT();

    for (int ch = 0; ch < nch; ch++) {
        if (ch + 1 < nch) {
            load_chunk(ch + 1, (ch + 1) & 1);
            CP_COMMIT();
            asm volatile("cp.async.wait_group 1;" ::: "memory");
        } else {
            asm volatile("cp.async.wait_group 0;" ::: "memory");
        }
        __syncthreads();

        const uint32_t base = us + (ch & 1) * STG;
        const uint32_t uA = base, uAl = base + TSZ, uB = base + 2 * TSZ, uBl = base + 3 * TSZ;
#pragma unroll
        for (int ks = 0; ks < 4; ks++) {
            const int kk = ks * 16;
            uint32_t ah[2][4], al[2][4];
            {
                int ar = (lane & 7) + ((lane >> 3) & 1) * 8;
                int ac = kk + ((lane >> 4) & 1) * 8;
#pragma unroll
                for (int mf = 0; mf < 2; mf++) {
                    uint32_t off = (uint32_t)((m0w + mf * 16 + ar) * PITCH + ac) * 2;
                    ldsm4(ah[mf], uA + off);
                    ldsm4(al[mf], uAl + off);
                }
            }
            uint32_t bh[2][4], bl[2][4];
            {
                int br = ((lane >> 4) & 1) * 8 + (lane & 7);
                int bc = kk + ((lane >> 3) & 1) * 8;
#pragma unroll
                for (int nb2 = 0; nb2 < 2; nb2++) {
                    uint32_t off = (uint32_t)((n0w + nb2 * 16 + br) * PITCH + bc) * 2;
                    ldsm4(bh[nb2], uB + off);
                    ldsm4(bl[nb2], uBl + off);
                }
            }
#pragma unroll
            for (int mf = 0; mf < 2; mf++)
#pragma unroll
                for (int nf = 0; nf < 4; nf++) {
                    const uint32_t* B0 = &bh[nf >> 1][(nf & 1) * 2];
                    const uint32_t* B1 = &bl[nf >> 1][(nf & 1) * 2];
                    mma16816(acc[mf][nf], ah[mf], B0);
                    mma16816(acc[mf][nf], al[mf], B0);
                    mma16816(acc[mf][nf], ah[mf], B1);
                }
        }
        __syncthreads();
    }

    // epilogue
    const int rq = lane >> 2, cq = (lane & 3) * 2;
#pragma unroll
    for (int mf = 0; mf < 2; mf++) {
#pragma unroll
        for (int nf = 0; nf < 4; nf++) {
            int col = nb0 + n0w + nf * 8 + cq;
            float b0 = 0.f, b1 = 0.f;
            if (bias) { b0 = __ldg(&bias[col]); b1 = __ldg(&bias[col + 1]); }
            int row0 = r0 + m0w + mf * 16 + rq;
#pragma unroll
            for (int half = 0; half < 2; half++) {
                int row = row0 + half * 8;
                if (row < M) {
                    float ox = acc[mf][nf][half * 2 + 0] + b0;
                    float oy = acc[mf][nf][half * 2 + 1] + b1;
                    if (act) { ox = fmaxf(ox, 0.f); oy = fmaxf(oy, 0.f); }
                    size_t idx = (size_t)row * HD + col;
                    if (outf) *(float2*)&outf[idx] = make_float2(ox, oy);
                    if (outhi) {
                        __nv_bfloat16 h0 = __float2bfloat16_rn(ox);
                        __nv_bfloat16 h1 = __float2bfloat16_rn(oy);
                        *(__nv_bfloat162*)&outhi[idx] = {h0, h1};
                        *(__nv_bfloat162*)&outlo[idx] =
                            {__float2bfloat16_rn(ox - __bfloat162float(h0)),
                             __float2bfloat16_rn(oy - __bfloat162float(h1))};
                    }
                }
            }
        }
    }
}

// ---------------- fused edge + segmented mean: warp-per-node, 2-edge pipelined ----------------
#define ESEG_BLOCKS 1563
__global__ __launch_bounds__(256) void k_edge_seg(
    const float* __restrict__ z, const int* __restrict__ src,
    const float* __restrict__ w, const float* __restrict__ W1l, int n)
{
    __shared__ float sc[3][HD];
    const int tid  = threadIdx.x;
    const int lane = tid & 31;
    const int wloc = tid >> 5;

    if (tid < HD) {
        sc[0][tid] = W1l[(size_t)tid * KE + HD + 0];
        sc[1][tid] = W1l[(size_t)tid * KE + HD + 1];
        sc[2][tid] = W1l[(size_t)tid * KE + HD + 2];
    }
    __syncthreads();

    const int f0 = lane * 8;
    float c0[8], c1[8], c2[8];
#pragma unroll
    for (int j = 0; j < 8; j++) {
        c0[j] = sc[0][f0 + j];
        c1[j] = sc[1][f0 + j];
        c2[j] = sc[2][f0 + j];
    }

    const int gwarp  = blockIdx.x * 8 + wloc;
    const int nwarps = ESEG_BLOCKS * 8;

    for (int v = gwarp; v < n; v += nwarps) {
        const int lo = g_rowptr[v], hi = g_rowptr[v + 1];
        float a[8];
#pragma unroll
        for (int j = 0; j < 8; j++) a[j] = 0.f;

        int i = lo;
        for (; i + 2 <= hi; i += 2) {
            int e0 = __ldg(&g_esorted[i]);
            int e1 = __ldg(&g_esorted[i + 1]);
            int s0 = __ldg(&src[e0]);
            int s1 = __ldg(&src[e1]);
            float w00 = __ldg(&w[(size_t)e0 * 3 + 0]);
            float w01 = __ldg(&w[(size_t)e0 * 3 + 1]);
            float w02 = __ldg(&w[(size_t)e0 * 3 + 2]);
            float w10 = __ldg(&w[(size_t)e1 * 3 + 0]);
            float w11 = __ldg(&w[(size_t)e1 * 3 + 1]);
            float w12 = __ldg(&w[(size_t)e1 * 3 + 2]);
            const float4* zr0 = (const float4*)&z[(size_t)s0 * HD];
            const float4* zr1 = (const float4*)&z[(size_t)s1 * HD];
            float4 za0 = __ldg(&zr0[lane * 2 + 0]);
            float4 zb0 = __ldg(&zr0[lane * 2 + 1]);
            float4 za1 = __ldg(&zr1[lane * 2 + 0]);
            float4 zb1 = __ldg(&zr1[lane * 2 + 1]);
            float t0[8] = {za0.x, za0.y, za0.z, za0.w, zb0.x, zb0.y, zb0.z, zb0.w};
            float t1[8] = {za1.x, za1.y, za1.z, za1.w, zb1.x, zb1.y, zb1.z, zb1.w};
#pragma unroll
            for (int j = 0; j < 8; j++) {
                float v0 = t0[j] + c0[j] * w00 + c1[j] * w01 + c2[j] * w02;
                a[j] += (v0 > 0.f) ? v0 : 0.01f * v0;
            }
#pragma unroll
            for (int j = 0; j < 8; j++) {
                float v1 = t1[j] + c0[j] * w10 + c1[j] * w11 + c2[j] * w12;
                a[j] += (v1 > 0.f) ? v1 : 0.01f * v1;
            }
        }
        if (i < hi) {
            int e = __ldg(&g_esorted[i]);
            int s = __ldg(&src[e]);
            float w0 = __ldg(&w[(size_t)e * 3 + 0]);
            float w1 = __ldg(&w[(size_t)e * 3 + 1]);
            float w2 = __ldg(&w[(size_t)e * 3 + 2]);
            const float4* zr = (const float4*)&z[(size_t)s * HD];
            float4 za = __ldg(&zr[lane * 2 + 0]);
            float4 zb = __ldg(&zr[lane * 2 + 1]);
            float t[8] = {za.x, za.y, za.z, za.w, zb.x, zb.y, zb.z, zb.w};
#pragma unroll
            for (int j = 0; j < 8; j++) {
                float val = t[j] + c0[j] * w0 + c1[j] * w1 + c2[j] * w2;
                a[j] += (val > 0.f) ? val : 0.01f * val;
            }
        }
        const float inv = g_inv[v];
        uint32_t hpack[4], lpack[4];
#pragma unroll
        for (int j = 0; j < 4; j++) {
            float r0v = a[j * 2 + 0] * inv;
            float r1v = a[j * 2 + 1] * inv;
            __nv_bfloat16 h0 = __float2bfloat16_rn(r0v);
            __nv_bfloat16 h1 = __float2bfloat16_rn(r1v);
            __nv_bfloat162 hp = {h0, h1};
            __nv_bfloat162 lp = {__float2bfloat16_rn(r0v - __bfloat162float(h0)),
                                 __float2bfloat16_rn(r1v - __bfloat162float(h1))};
            hpack[j] = *(uint32_t*)&hp;
            lpack[j] = *(uint32_t*)&lp;
        }
        size_t idx = (size_t)v * HD + f0;
        *(uint4*)&g_nhi[idx] = *(uint4*)hpack;
        *(uint4*)&g_nlo[idx] = *(uint4*)lpack;
    }
}

// ---------------- head ----------------
__global__ void k_head2(const float* __restrict__ x, const float* __restrict__ Wh2,
                        const float* __restrict__ bh2, float* __restrict__ out, int n) {
    int gtid = blockIdx.x * blockDim.x + threadIdx.x;
    int v = gtid >> 5;
    int lane = gtid & 31;
    if (v >= n) return;
    float s = 0.f;
#pragma unroll
    for (int k = lane; k < HD; k += 32) s += x[(size_t)v * HD + k] * Wh2[k];
#pragma unroll
    for (int o = 16; o; o >>= 1) s += __shfl_xor_sync(0xffffffffu, s, o);
    if (lane == 0) out[v] = s + bh2[0];
}

// ---------------- host ----------------
extern "C" void kernel_launch(void* const* d_in, const int* in_sizes, int n_in,
                              void* d_out, int out_size) {
    const int*   gate = (const int*)  d_in[0];
    const int*   src  = (const int*)  d_in[1];
    const int*   dst  = (const int*)  d_in[2];
    const float* w    = (const float*)d_in[3];
    const float* emb  = (const float*)d_in[4];
    const float* W1   = (const float*)d_in[5];
    const float* W2   = (const float*)d_in[6];
    const float* b2   = (const float*)d_in[7];
    const float* Wh1  = (const float*)d_in[8];
    const float* bh1  = (const float*)d_in[9];
    const float* Wh2  = (const float*)d_in[10];
    const float* bh2  = (const float*)d_in[11];
    float* out = (float*)d_out;

    int n = in_sizes[0];
    int e = in_sizes[1];

    static cudaStream_t s2 = nullptr;
    static cudaEvent_t evFork = nullptr, evCSR = nullptr;
    if (!s2) {   // first call = uncaptured correctness run
        cudaFuncSetAttribute(k_gemm_mma, cudaFuncAttributeMaxDynamicSharedMemorySize, 2 * STG);
        cudaStreamCreateWithFlags(&s2, cudaStreamNonBlocking);
        cudaEventCreateWithFlags(&evFork, cudaEventDisableTiming);
        cudaEventCreateWithFlags(&evCSR, cudaEventDisableTiming);
    }

    void* p;
    cudaGetSymbolAddress(&p, g_ahi); __nv_bfloat16* ahi = (__nv_bfloat16*)p;
    cudaGetSymbolAddress(&p, g_alo); __nv_bfloat16* alo = (__nv_bfloat16*)p;
    cudaGetSymbolAddress(&p, g_bhi); __nv_bfloat16* bhi = (__nv_bfloat16*)p;
    cudaGetSymbolAddress(&p, g_blo); __nv_bfloat16* blo = (__nv_bfloat16*)p;
    cudaGetSymbolAddress(&p, g_nhi); __nv_bfloat16* nhi = (__nv_bfloat16*)p;
    cudaGetSymbolAddress(&p, g_nlo); __nv_bfloat16* nlo = (__nv_bfloat16*)p;
    cudaGetSymbolAddress(&p, g_z);   float* z = (float*)p;
    cudaGetSymbolAddress(&p, g_zem); float* zem = (float*)p;
    cudaGetSymbolAddress(&p, g_w1hi); __nv_bfloat16* w1hi = (__nv_bfloat16*)p;
    cudaGetSymbolAddress(&p, g_w1lo); __nv_bfloat16* w1lo = (__nv_bfloat16*)p;
    cudaGetSymbolAddress(&p, g_w2hi); __nv_bfloat16* w2hi = (__nv_bfloat16*)p;
    cudaGetSymbolAddress(&p, g_w2lo); __nv_bfloat16* w2lo = (__nv_bfloat16*)p;
    cudaGetSymbolAddress(&p, g_whhi); __nv_bfloat16* whhi = (__nv_bfloat16*)p;
    cudaGetSymbolAddress(&p, g_whlo); __nv_bfloat16* whlo = (__nv_bfloat16*)p;
    cudaGetSymbolAddress(&p, g_ehi); __nv_bfloat16* ehi = (__nv_bfloat16*)p;
    cudaGetSymbolAddress(&p, g_elo); __nv_bfloat16* elo = (__nv_bfloat16*)p;

    // ---- fork s2 FROM the capture-origin stream (required for graph capture) ----
    cudaEventRecord(evFork, 0);
    cudaStreamWaitEvent(s2, evFork, 0);

    // ---- CSR prep on s2 (only needed at the first edge_seg) ----
    k_zero_deg<<<(n + 255) / 256, 256, 0, s2>>>(n);
    k_deg     <<<(e + 255) / 256, 256, 0, s2>>>(dst, e);
    k_scan    <<<1, 1024, 0, s2>>>(n);
    k_scatter <<<(e + 255) / 256, 256, 0, s2>>>(dst, e);
    k_segsort <<<(n + 255) / 256, 256, 0, s2>>>(n);
    cudaEventRecord(evCSR, s2);

    // ---- weight/emb prep + layer-0 z on main stream (concurrent with CSR) ----
    k_wsplit <<<(W1SZ + W2SZ + WHSZ + EMBSZ + 255) / 256, 256>>>(W1, W2, Wh1, emb);
    k_init   <<<((size_t)n * HD + 255) / 256, 256>>>(gate, emb, n);

    __nv_bfloat16 *pah = ahi, *pal = alo, *pbh = bhi, *pbl = blo;
    dim3 gg((n + 127) / 128, 2);
    dim3 gt(1, 2);

    // zem = emb @ W1_0^T  (29-row GEMM; rows independent -> bit-identical to per-node)
    k_gemm_mma<<<gt, 512, 2 * STG>>>(ehi, elo, ehi, elo, w1hi, w1lo,
                                     nullptr, zem, nullptr, nullptr, HD, HD, NGT, 0);
    k_gather0<<<((size_t)n * HD + 255) / 256, 256>>>(gate, n);

    // join: CSR must be ready before first edge_seg
    cudaStreamWaitEvent(0, evCSR, 0);

    for (int l = 0; l < NL; l++) {
        const float* W1l = W1 + (size_t)l * HD * KE;
        if (l > 0) {
            k_gemm_mma<<<gg, 512, 2 * STG>>>(pah, pal, pah, pal,
                                             w1hi + (size_t)l * HD * HD, w1lo + (size_t)l * HD * HD,
                                             nullptr, z, nullptr, nullptr, HD, HD, n, 0);
        }
        k_edge_seg<<<ESEG_BLOCKS, 256>>>(z, src, w, W1l, n);
        k_gemm_mma<<<gg, 512, 2 * STG>>>(pah, pal, nhi, nlo,
                                         w2hi + (size_t)l * HD * 512, w2lo + (size_t)l * HD * 512,
                                         b2 + (size_t)l * HD, nullptr, pbh, pbl, 512, 512, n, 1);
        __nv_bfloat16* t;
        t = pah; pah = pbh; pbh = t;
        t = pal; pal = pbl; pbl = t;
    }
    k_gemm_mma<<<gg, 512, 2 * STG>>>(pah, pal, pah, pal, whhi, whlo,
                                     bh1, z, nullptr, nullptr, HD, HD, n, 1);
    k_head2<<<((size_t)n * 32 + 255) / 256, 256>>>(z, Wh2, bh2, out, n);
}

// round 13
// speedup vs baseline: 1.0982x; 1.0119x over previous
#include <cuda_runtime.h>
#include <cuda_bf16.h>
#include <cstdint>

#define NN 100000
#define NE 800000
#define HD 256
#define KE 259      // H + 3 edge features
#define NL 6
#define NGT 29      // gate types

// ---------------- scratch (static device globals) ----------------
static __device__ __align__(16) __nv_bfloat16 g_ahi[(size_t)NN * HD];
static __device__ __align__(16) __nv_bfloat16 g_alo[(size_t)NN * HD];
static __device__ __align__(16) __nv_bfloat16 g_bhi[(size_t)NN * HD];
static __device__ __align__(16) __nv_bfloat16 g_blo[(size_t)NN * HD];
static __device__ __align__(16) __nv_bfloat16 g_nhi[(size_t)NN * HD];
static __device__ __align__(16) __nv_bfloat16 g_nlo[(size_t)NN * HD];
static __device__ float g_z[(size_t)NN * HD];
#define W1SZ (NL * HD * HD)
#define W2SZ (NL * HD * 512)
#define WHSZ (HD * HD)
#define EMBSZ (NGT * HD)
static __device__ __align__(16) __nv_bfloat16 g_w1hi[W1SZ], g_w1lo[W1SZ];
static __device__ __align__(16) __nv_bfloat16 g_w2hi[W2SZ], g_w2lo[W2SZ];
static __device__ __align__(16) __nv_bfloat16 g_whhi[WHSZ], g_whlo[WHSZ];
static __device__ __align__(16) __nv_bfloat16 g_ehi[EMBSZ], g_elo[EMBSZ];
static __device__ float g_zem[EMBSZ];

static __device__ float g_inv[NN];
static __device__ int   g_deg[NN];
static __device__ int   g_rowptr[NN + 1];
static __device__ int   g_cursor[NN];
static __device__ int   g_esorted[NE];

// ---------------- preprocessing: deterministic CSR by dst ----------------
__global__ void k_zero_deg(int n) {
    int i = blockIdx.x * blockDim.x + threadIdx.x;
    if (i < n) g_deg[i] = 0;
}

__global__ void k_deg(const int* __restrict__ dst, int e) {
    int i = blockIdx.x * blockDim.x + threadIdx.x;
    if (i < e) atomicAdd(&g_deg[dst[i]], 1);
}

__global__ void k_scan(int n) {
    __shared__ int s[1024];
    int t = threadIdx.x;
    int per = (n + 1023) / 1024;
    int lo = t * per;
    int hi = lo + per; if (hi > n) hi = n;
    int sum = 0;
    for (int i = lo; i < hi; i++) sum += g_deg[i];
    s[t] = sum;
    __syncthreads();
    for (int off = 1; off < 1024; off <<= 1) {
        int v = (t >= off) ? s[t - off] : 0;
        __syncthreads();
        s[t] += v;
        __syncthreads();
    }
    int run = s[t] - sum;
    for (int i = lo; i < hi; i++) {
        g_rowptr[i] = run;
        g_cursor[i] = run;
        g_inv[i] = 1.0f / fmaxf((float)g_deg[i], 1.0f);
        run += g_deg[i];
    }
    if (t == 1023) g_rowptr[n] = s[1023];
}

__global__ void k_scatter(const int* __restrict__ dst, int e) {
    int i = blockIdx.x * blockDim.x + threadIdx.x;
    if (i < e) {
        int d = dst[i];
        int pos = atomicAdd(&g_cursor[d], 1);
        g_esorted[pos] = i;
    }
}

__global__ void k_segsort(int n) {
    int v = blockIdx.x * blockDim.x + threadIdx.x;
    if (v >= n) return;
    int lo = g_rowptr[v], hi = g_rowptr[v + 1];
    for (int i = lo + 1; i < hi; i++) {
        int key = g_esorted[i];
        int j = i - 1;
        while (j >= lo && g_esorted[j] > key) { g_esorted[j + 1] = g_esorted[j]; j--; }
        g_esorted[j + 1] = key;
    }
}

// ---------------- weight + emb pre-split ----------------
__global__ void k_wsplit(const float* __restrict__ W1, const float* __restrict__ W2,
                         const float* __restrict__ Wh1, const float* __restrict__ emb) {
    int i = blockIdx.x * blockDim.x + threadIdx.x;
    float v; __nv_bfloat16* dh; __nv_bfloat16* dl; int o;
    if (i < W1SZ) {
        int l = i / (HD * HD), rem = i % (HD * HD);
        int row = rem / HD, col = rem % HD;
        v = W1[(size_t)l * HD * KE + (size_t)row * KE + col];
        dh = g_w1hi; dl = g_w1lo; o = i;
    } else if (i < W1SZ + W2SZ) {
        o = i - W1SZ;
        v = W2[o];
        dh = g_w2hi; dl = g_w2lo;
    } else if (i < W1SZ + W2SZ + WHSZ) {
        o = i - W1SZ - W2SZ;
        v = Wh1[o];
        dh = g_whhi; dl = g_whlo;
    } else if (i < W1SZ + W2SZ + WHSZ + EMBSZ) {
        o = i - W1SZ - W2SZ - WHSZ;
        v = emb[o];
        dh = g_ehi; dl = g_elo;
    } else return;
    __nv_bfloat16 h = __float2bfloat16_rn(v);
    dh[o] = h;
    dl[o] = __float2bfloat16_rn(v - __bfloat162float(h));
}

// ---------------- warp-MMA helpers ----------------
__device__ __forceinline__ uint32_t s2u(const void* p) {
    return (uint32_t)__cvta_generic_to_shared(p);
}
__device__ __forceinline__ void ldsm4(uint32_t* r, uint32_t addr) {
    asm volatile("ldmatrix.sync.aligned.m8n8.x4.shared.b16 {%0,%1,%2,%3}, [%4];"
        : "=r"(r[0]), "=r"(r[1]), "=r"(r[2]), "=r"(r[3]) : "r"(addr));
}
__device__ __forceinline__ void mma16816(float* d, const uint32_t* a, const uint32_t* b) {
    asm volatile("mma.sync.aligned.m16n8k16.row.col.f32.bf16.bf16.f32 "
        "{%0,%1,%2,%3}, {%4,%5,%6,%7}, {%8,%9}, {%0,%1,%2,%3};"
        : "+f"(d[0]), "+f"(d[1]), "+f"(d[2]), "+f"(d[3])
        : "r"(a[0]), "r"(a[1]), "r"(a[2]), "r"(a[3]), "r"(b[0]), "r"(b[1]));
}
__device__ __forceinline__ void cpa16(uint32_t d, const void* s) {
    asm volatile("cp.async.ca.shared.global [%0], [%1], 16;" :: "r"(d), "l"(s));
}
#define CP_COMMIT() asm volatile("cp.async.commit_group;" ::: "memory")

// ---------------- bf16x3 MMA GEMM, 512 threads, BK=64, double-buffered ----------------
// ridx: optional row-index indirection for the A0 (kc<HD) part (29-row emb table).
#define PITCH 72
#define TSZ   18432
#define STG   73728
__global__ __launch_bounds__(512) void k_gemm_mma(
    const __nv_bfloat16* __restrict__ A0h, const __nv_bfloat16* __restrict__ A0l,
    const __nv_bfloat16* __restrict__ A1h, const __nv_bfloat16* __restrict__ A1l,
    const __nv_bfloat16* __restrict__ Bh,  const __nv_bfloat16* __restrict__ Bl,
    const float* __restrict__ bias, const int* __restrict__ ridx,
    float* __restrict__ outf, __nv_bfloat16* __restrict__ outhi, __nv_bfloat16* __restrict__ outlo,
    int K, int ws, int M, int act)
{
    extern __shared__ char smem[];
    const uint32_t us = s2u(smem);

    const int tid  = threadIdx.x;
    const int lane = tid & 31;
    const int wid  = tid >> 5;
    const int r0   = blockIdx.x * 128;
    const int nb0  = blockIdx.y * 128;
    const int m0w  = (wid >> 2) * 32;
    const int n0w  = (wid & 3) * 32;

    float acc[2][4][4];
#pragma unroll
    for (int i = 0; i < 2; i++)
#pragma unroll
        for (int j = 0; j < 4; j++)
#pragma unroll
            for (int t = 0; t < 4; t++) acc[i][j][t] = 0.f;

    const int nch = K >> 6;
    const int lr  = tid >> 2;
    const int lcb = (tid & 3) * 8;

    auto load_chunk = [&](int ch, int stage) {
        const int kc = ch << 6;
        const __nv_bfloat16* Ah = (kc < HD) ? A0h : A1h;
        const __nv_bfloat16* Al = (kc < HD) ? A0l : A1l;
        const int acol = (kc < HD) ? kc : (kc - HD);
        const uint32_t base = us + stage * STG;
        int g = r0 + lr; if (g >= M) g = M - 1;
        if (ridx && kc < HD) g = __ldg(&ridx[g]);
#pragma unroll
        for (int gi = 0; gi < 2; gi++) {
            int c = lcb + gi * 32;
            uint32_t so = (uint32_t)(lr * PITCH + c) * 2;
            cpa16(base + so,           &Ah[(size_t)g * HD + acol + c]);
            cpa16(base + TSZ + so,     &Al[(size_t)g * HD + acol + c]);
            cpa16(base + 2 * TSZ + so, &Bh[(size_t)(nb0 + lr) * ws + kc + c]);
            cpa16(base + 3 * TSZ + so, &Bl[(size_t)(nb0 + lr) * ws + kc + c]);
        }
    };

    load_chunk(0, 0);
    CP_COMMIT();

    for (int ch = 0; ch < nch; ch++) {
        if (ch + 1 < nch) {
            load_chunk(ch + 1, (ch + 1) & 1);
            CP_COMMIT();
            asm volatile("cp.async.wait_group 1;" ::: "memory");
        } else {
            asm volatile("cp.async.wait_group 0;" ::: "memory");
        }
        __syncthreads();

        const uint32_t base = us + (ch & 1) * STG;
        const uint32_t uA = base, uAl = base + TSZ, uB = base + 2 * TSZ, uBl = base + 3 * TSZ;
#pragma unroll
        for (int ks = 0; ks < 4; ks++) {
            const int kk = ks * 16;
            uint32_t ah[2][4], al[2][4];
            {
                int ar = (lane & 7) + ((lane >> 3) & 1) * 8;
                int ac = kk + ((lane >> 4) & 1) * 8;
#pragma unroll
                for (int mf = 0; mf < 2; mf++) {
                    uint32_t off = (uint32_t)((m0w + mf * 16 + ar) * PITCH + ac) * 2;
                    ldsm4(ah[mf], uA + off);
                    ldsm4(al[mf], uAl + off);
                }
            }
            uint32_t bh[2][4], bl[2][4];
            {
                int br = ((lane >> 4) & 1) * 8 + (lane & 7);
                int bc = kk + ((lane >> 3) & 1) * 8;
#pragma unroll
                for (int nb2 = 0; nb2 < 2; nb2++) {
                    uint32_t off = (uint32_t)((n0w + nb2 * 16 + br) * PITCH + bc) * 2;
                    ldsm4(bh[nb2], uB + off);
                    ldsm4(bl[nb2], uBl + off);
                }
            }
#pragma unroll
            for (int mf = 0; mf < 2; mf++)
#pragma unroll
                for (int nf = 0; nf < 4; nf++) {
                    const uint32_t* B0 = &bh[nf >> 1][(nf & 1) * 2];
                    const uint32_t* B1 = &bl[nf >> 1][(nf & 1) * 2];
                    mma16816(acc[mf][nf], ah[mf], B0);
                    mma16816(acc[mf][nf], al[mf], B0);
                    mma16816(acc[mf][nf], ah[mf], B1);
                }
        }
        __syncthreads();
    }

    // epilogue
    const int rq = lane >> 2, cq = (lane & 3) * 2;
#pragma unroll
    for (int mf = 0; mf < 2; mf++) {
#pragma unroll
        for (int nf = 0; nf < 4; nf++) {
            int col = nb0 + n0w + nf * 8 + cq;
            float b0 = 0.f, b1 = 0.f;
            if (bias) { b0 = __ldg(&bias[col]); b1 = __ldg(&bias[col + 1]); }
            int row0 = r0 + m0w + mf * 16 + rq;
#pragma unroll
            for (int half = 0; half < 2; half++) {
                int row = row0 + half * 8;
                if (row < M) {
                    float ox = acc[mf][nf][half * 2 + 0] + b0;
                    float oy = acc[mf][nf][half * 2 + 1] + b1;
                    if (act) { ox = fmaxf(ox, 0.f); oy = fmaxf(oy, 0.f); }
                    size_t idx = (size_t)row * HD + col;
                    if (outf) *(float2*)&outf[idx] = make_float2(ox, oy);
                    if (outhi) {
                        __nv_bfloat16 h0 = __float2bfloat16_rn(ox);
                        __nv_bfloat16 h1 = __float2bfloat16_rn(oy);
                        *(__nv_bfloat162*)&outhi[idx] = {h0, h1};
                        *(__nv_bfloat162*)&outlo[idx] =
                            {__float2bfloat16_rn(ox - __bfloat162float(h0)),
                             __float2bfloat16_rn(oy - __bfloat162float(h1))};
                    }
                }
            }
        }
    }
}

// ---------------- fused edge + segmented mean: warp-per-node, 2-edge pipelined ----------------
// gate0: if non-null, z rows are indexed by gate0[src_e] (29-row zem table, L1-resident).
#define ESEG_BLOCKS 1563
__global__ __launch_bounds__(256) void k_edge_seg(
    const float* __restrict__ z, const int* __restrict__ src,
    const float* __restrict__ w, const float* __restrict__ W1l,
    const int* __restrict__ gate0, int n)
{
    __shared__ float sc[3][HD];
    const int tid  = threadIdx.x;
    const int lane = tid & 31;
    const int wloc = tid >> 5;

    if (tid < HD) {
        sc[0][tid] = W1l[(size_t)tid * KE + HD + 0];
        sc[1][tid] = W1l[(size_t)tid * KE + HD + 1];
        sc[2][tid] = W1l[(size_t)tid * KE + HD + 2];
    }
    __syncthreads();

    const int f0 = lane * 8;
    float c0[8], c1[8], c2[8];
#pragma unroll
    for (int j = 0; j < 8; j++) {
        c0[j] = sc[0][f0 + j];
        c1[j] = sc[1][f0 + j];
        c2[j] = sc[2][f0 + j];
    }

    const int gwarp  = blockIdx.x * 8 + wloc;
    const int nwarps = ESEG_BLOCKS * 8;

    for (int v = gwarp; v < n; v += nwarps) {
        const int lo = g_rowptr[v], hi = g_rowptr[v + 1];
        float a[8];
#pragma unroll
        for (int j = 0; j < 8; j++) a[j] = 0.f;

        int i = lo;
        for (; i + 2 <= hi; i += 2) {
            int e0 = __ldg(&g_esorted[i]);
            int e1 = __ldg(&g_esorted[i + 1]);
            int s0 = __ldg(&src[e0]);
            int s1 = __ldg(&src[e1]);
            if (gate0) { s0 = __ldg(&gate0[s0]); s1 = __ldg(&gate0[s1]); }
            float w00 = __ldg(&w[(size_t)e0 * 3 + 0]);
            float w01 = __ldg(&w[(size_t)e0 * 3 + 1]);
            float w02 = __ldg(&w[(size_t)e0 * 3 + 2]);
            float w10 = __ldg(&w[(size_t)e1 * 3 + 0]);
            float w11 = __ldg(&w[(size_t)e1 * 3 + 1]);
            float w12 = __ldg(&w[(size_t)e1 * 3 + 2]);
            const float4* zr0 = (const float4*)&z[(size_t)s0 * HD];
            const float4* zr1 = (const float4*)&z[(size_t)s1 * HD];
            float4 za0 = __ldg(&zr0[lane * 2 + 0]);
            float4 zb0 = __ldg(&zr0[lane * 2 + 1]);
            float4 za1 = __ldg(&zr1[lane * 2 + 0]);
            float4 zb1 = __ldg(&zr1[lane * 2 + 1]);
            float t0[8] = {za0.x, za0.y, za0.z, za0.w, zb0.x, zb0.y, zb0.z, zb0.w};
            float t1[8] = {za1.x, za1.y, za1.z, za1.w, zb1.x, zb1.y, zb1.z, zb1.w};
#pragma unroll
            for (int j = 0; j < 8; j++) {
                float v0 = t0[j] + c0[j] * w00 + c1[j] * w01 + c2[j] * w02;
                a[j] += (v0 > 0.f) ? v0 : 0.01f * v0;
            }
#pragma unroll
            for (int j = 0; j < 8; j++) {
                float v1 = t1[j] + c0[j] * w10 + c1[j] * w11 + c2[j] * w12;
                a[j] += (v1 > 0.f) ? v1 : 0.01f * v1;
            }
        }
        if (i < hi) {
            int e = __ldg(&g_esorted[i]);
            int s = __ldg(&src[e]);
            if (gate0) s = __ldg(&gate0[s]);
            float w0 = __ldg(&w[(size_t)e * 3 + 0]);
            float w1 = __ldg(&w[(size_t)e * 3 + 1]);
            float w2 = __ldg(&w[(size_t)e * 3 + 2]);
            const float4* zr = (const float4*)&z[(size_t)s * HD];
            float4 za = __ldg(&zr[lane * 2 + 0]);
            float4 zb = __ldg(&zr[lane * 2 + 1]);
            float t[8] = {za.x, za.y, za.z, za.w, zb.x, zb.y, zb.z, zb.w};
#pragma unroll
            for (int j = 0; j < 8; j++) {
                float val = t[j] + c0[j] * w0 + c1[j] * w1 + c2[j] * w2;
                a[j] += (val > 0.f) ? val : 0.01f * val;
            }
        }
        const float inv = g_inv[v];
        uint32_t hpack[4], lpack[4];
#pragma unroll
        for (int j = 0; j < 4; j++) {
            float r0v = a[j * 2 + 0] * inv;
            float r1v = a[j * 2 + 1] * inv;
            __nv_bfloat16 h0 = __float2bfloat16_rn(r0v);
            __nv_bfloat16 h1 = __float2bfloat16_rn(r1v);
            __nv_bfloat162 hp = {h0, h1};
            __nv_bfloat162 lp = {__float2bfloat16_rn(r0v - __bfloat162float(h0)),
                                 __float2bfloat16_rn(r1v - __bfloat162float(h1))};
            hpack[j] = *(uint32_t*)&hp;
            lpack[j] = *(uint32_t*)&lp;
        }
        size_t idx = (size_t)v * HD + f0;
        *(uint4*)&g_nhi[idx] = *(uint4*)hpack;
        *(uint4*)&g_nlo[idx] = *(uint4*)lpack;
    }
}

// ---------------- head ----------------
__global__ void k_head2(const float* __restrict__ x, const float* __restrict__ Wh2,
                        const float* __restrict__ bh2, float* __restrict__ out, int n) {
    int gtid = blockIdx.x * blockDim.x + threadIdx.x;
    int v = gtid >> 5;
    int lane = gtid & 31;
    if (v >= n) return;
    float s = 0.f;
#pragma unroll
    for (int k = lane; k < HD; k += 32) s += x[(size_t)v * HD + k] * Wh2[k];
#pragma unroll
    for (int o = 16; o; o >>= 1) s += __shfl_xor_sync(0xffffffffu, s, o);
    if (lane == 0) out[v] = s + bh2[0];
}

// ---------------- host ----------------
extern "C" void kernel_launch(void* const* d_in, const int* in_sizes, int n_in,
                              void* d_out, int out_size) {
    const int*   gate = (const int*)  d_in[0];
    const int*   src  = (const int*)  d_in[1];
    const int*   dst  = (const int*)  d_in[2];
    const float* w    = (const float*)d_in[3];
    const float* emb  = (const float*)d_in[4];
    const float* W1   = (const float*)d_in[5];
    const float* W2   = (const float*)d_in[6];
    const float* b2   = (const float*)d_in[7];
    const float* Wh1  = (const float*)d_in[8];
    const float* bh1  = (const float*)d_in[9];
    const float* Wh2  = (const float*)d_in[10];
    const float* bh2  = (const float*)d_in[11];
    float* out = (float*)d_out;

    int n = in_sizes[0];
    int e = in_sizes[1];

    static cudaStream_t s2 = nullptr;
    static cudaEvent_t evFork = nullptr, evCSR = nullptr;
    if (!s2) {   // first call = uncaptured correctness run
        cudaFuncSetAttribute(k_gemm_mma, cudaFuncAttributeMaxDynamicSharedMemorySize, 2 * STG);
        cudaStreamCreateWithFlags(&s2, cudaStreamNonBlocking);
        cudaEventCreateWithFlags(&evFork, cudaEventDisableTiming);
        cudaEventCreateWithFlags(&evCSR, cudaEventDisableTiming);
    }

    void* p;
    cudaGetSymbolAddress(&p, g_ahi); __nv_bfloat16* ahi = (__nv_bfloat16*)p;
    cudaGetSymbolAddress(&p, g_alo); __nv_bfloat16* alo = (__nv_bfloat16*)p;
    cudaGetSymbolAddress(&p, g_bhi); __nv_bfloat16* bhi = (__nv_bfloat16*)p;
    cudaGetSymbolAddress(&p, g_blo); __nv_bfloat16* blo = (__nv_bfloat16*)p;
    cudaGetSymbolAddress(&p, g_nhi); __nv_bfloat16* nhi = (__nv_bfloat16*)p;
    cudaGetSymbolAddress(&p, g_nlo); __nv_bfloat16* nlo = (__nv_bfloat16*)p;
    cudaGetSymbolAddress(&p, g_z);   float* z = (float*)p;
    cudaGetSymbolAddress(&p, g_zem); float* zem = (float*)p;
    cudaGetSymbolAddress(&p, g_w1hi); __nv_bfloat16* w1hi = (__nv_bfloat16*)p;
    cudaGetSymbolAddress(&p, g_w1lo); __nv_bfloat16* w1lo = (__nv_bfloat16*)p;
    cudaGetSymbolAddress(&p, g_w2hi); __nv_bfloat16* w2hi = (__nv_bfloat16*)p;
    cudaGetSymbolAddress(&p, g_w2lo); __nv_bfloat16* w2lo = (__nv_bfloat16*)p;
    cudaGetSymbolAddress(&p, g_whhi); __nv_bfloat16* whhi = (__nv_bfloat16*)p;
    cudaGetSymbolAddress(&p, g_whlo); __nv_bfloat16* whlo = (__nv_bfloat16*)p;
    cudaGetSymbolAddress(&p, g_ehi); __nv_bfloat16* ehi = (__nv_bfloat16*)p;
    cudaGetSymbolAddress(&p, g_elo); __nv_bfloat16* elo = (__nv_bfloat16*)p;

    // ---- fork s2 FROM the capture-origin stream (required for graph capture) ----
    cudaEventRecord(evFork, 0);
    cudaStreamWaitEvent(s2, evFork, 0);

    // ---- CSR prep on s2 (only needed at the first edge_seg) ----
    k_zero_deg<<<(n + 255) / 256, 256, 0, s2>>>(n);
    k_deg     <<<(e + 255) / 256, 256, 0, s2>>>(dst, e);
    k_scan    <<<1, 1024, 0, s2>>>(n);
    k_scatter <<<(e + 255) / 256, 256, 0, s2>>>(dst, e);
    k_segsort <<<(n + 255) / 256, 256, 0, s2>>>(n);
    cudaEventRecord(evCSR, s2);

    // ---- weight/emb prep + zem on main stream (concurrent with CSR) ----
    k_wsplit <<<(W1SZ + W2SZ + WHSZ + EMBSZ + 255) / 256, 256>>>(W1, W2, Wh1, emb);

    __nv_bfloat16 *pah = ahi, *pal = alo, *pbh = bhi, *pbl = blo;
    dim3 gg((n + 127) / 128, 2);
    dim3 gt(1, 2);

    // zem = emb @ W1_0^T  (29-row GEMM; bit-identical rows to per-node z0)
    k_gemm_mma<<<gt, 512, 2 * STG>>>(ehi, elo, ehi, elo, w1hi, w1lo,
                                     nullptr, nullptr, zem, nullptr, nullptr, HD, HD, NGT, 0);

    // join: CSR must be ready before first edge_seg
    cudaStreamWaitEvent(0, evCSR, 0);

    for (int l = 0; l < NL; l++) {
        const float* W1l = W1 + (size_t)l * HD * KE;
        if (l > 0) {
            k_gemm_mma<<<gg, 512, 2 * STG>>>(pah, pal, pah, pal,
                                             w1hi + (size_t)l * HD * HD, w1lo + (size_t)l * HD * HD,
                                             nullptr, nullptr, z, nullptr, nullptr, HD, HD, n, 0);
            k_edge_seg<<<ESEG_BLOCKS, 256>>>(z, src, w, W1l, nullptr, n);
            k_gemm_mma<<<gg, 512, 2 * STG>>>(pah, pal, nhi, nlo,
                                             w2hi + (size_t)l * HD * 512, w2lo + (size_t)l * HD * 512,
                                             b2 + (size_t)l * HD, nullptr, nullptr, pbh, pbl, 512, 512, n, 1);
        } else {
            // layer 0: z rows come from the 29-row zem table (gate-indirect)
            k_edge_seg<<<ESEG_BLOCKS, 256>>>(zem, src, w, W1l, gate, n);
            // node GEMM: A0 = emb tables gathered through gate (L1-resident)
            k_gemm_mma<<<gg, 512, 2 * STG>>>(ehi, elo, nhi, nlo,
                                             w2hi, w2lo,
                                             b2, gate, nullptr, pbh, pbl, 512, 512, n, 1);
        }
        __nv_bfloat16* t;
        t = pah; pah = pbh; pbh = t;
        t = pal; pal = pbl; pbl = t;
    }
    k_gemm_mma<<<gg, 512, 2 * STG>>>(pah, pal, pah, pal, whhi, whlo,
                                     bh1, nullptr, z, nullptr, nullptr, HD, HD, n, 1);
    k_head2<<<((size_t)n * 32 + 255) / 256, 256>>>(z, Wh2, bh2, out, n);
}

// round 14
// speedup vs baseline: 1.1057x; 1.0068x over previous
#include <cuda_runtime.h>
#include <cuda_bf16.h>
#include <cstdint>

#define NN 100000
#define NE 800000
#define HD 256
#define KE 259      // H + 3 edge features
#define NL 6
#define NGT 29      // gate types

// ---------------- scratch (static device globals) ----------------
static __device__ __align__(16) __nv_bfloat16 g_ahi[(size_t)NN * HD];
static __device__ __align__(16) __nv_bfloat16 g_alo[(size_t)NN * HD];
static __device__ __align__(16) __nv_bfloat16 g_bhi[(size_t)NN * HD];
static __device__ __align__(16) __nv_bfloat16 g_blo[(size_t)NN * HD];
static __device__ __align__(16) __nv_bfloat16 g_nhi[(size_t)NN * HD];
static __device__ __align__(16) __nv_bfloat16 g_nlo[(size_t)NN * HD];
static __device__ float g_z[(size_t)NN * HD];
#define W1SZ (NL * HD * HD)
#define W2SZ (NL * HD * 512)
#define WHSZ (HD * HD)
#define EMBSZ (NGT * HD)
static __device__ __align__(16) __nv_bfloat16 g_w1hi[W1SZ], g_w1lo[W1SZ];
static __device__ __align__(16) __nv_bfloat16 g_w2hi[W2SZ], g_w2lo[W2SZ];
static __device__ __align__(16) __nv_bfloat16 g_whhi[WHSZ], g_whlo[WHSZ];
static __device__ __align__(16) __nv_bfloat16 g_ehi[EMBSZ], g_elo[EMBSZ];
static __device__ float g_zem[EMBSZ];
static __device__ float g_part[(size_t)NN * 2];

static __device__ float g_inv[NN];
static __device__ int   g_deg[NN];
static __device__ int   g_rowptr[NN + 1];
static __device__ int   g_cursor[NN];
static __device__ int   g_esorted[NE];

// ---------------- preprocessing: deterministic CSR by dst ----------------
__global__ void k_zero_deg(int n) {
    int i = blockIdx.x * blockDim.x + threadIdx.x;
    if (i < n) g_deg[i] = 0;
}

__global__ void k_deg(const int* __restrict__ dst, int e) {
    int i = blockIdx.x * blockDim.x + threadIdx.x;
    if (i < e) atomicAdd(&g_deg[dst[i]], 1);
}

__global__ void k_scan(int n) {
    __shared__ int s[1024];
    int t = threadIdx.x;
    int per = (n + 1023) / 1024;
    int lo = t * per;
    int hi = lo + per; if (hi > n) hi = n;
    int sum = 0;
    for (int i = lo; i < hi; i++) sum += g_deg[i];
    s[t] = sum;
    __syncthreads();
    for (int off = 1; off < 1024; off <<= 1) {
        int v = (t >= off) ? s[t - off] : 0;
        __syncthreads();
        s[t] += v;
        __syncthreads();
    }
    int run = s[t] - sum;
    for (int i = lo; i < hi; i++) {
        g_rowptr[i] = run;
        g_cursor[i] = run;
        g_inv[i] = 1.0f / fmaxf((float)g_deg[i], 1.0f);
        run += g_deg[i];
    }
    if (t == 1023) g_rowptr[n] = s[1023];
}

__global__ void k_scatter(const int* __restrict__ dst, int e) {
    int i = blockIdx.x * blockDim.x + threadIdx.x;
    if (i < e) {
        int d = dst[i];
        int pos = atomicAdd(&g_cursor[d], 1);
        g_esorted[pos] = i;
    }
}

__global__ void k_segsort(int n) {
    int v = blockIdx.x * blockDim.x + threadIdx.x;
    if (v >= n) return;
    int lo = g_rowptr[v], hi = g_rowptr[v + 1];
    for (int i = lo + 1; i < hi; i++) {
        int key = g_esorted[i];
        int j = i - 1;
        while (j >= lo && g_esorted[j] > key) { g_esorted[j + 1] = g_esorted[j]; j--; }
        g_esorted[j + 1] = key;
    }
}

// ---------------- weight + emb pre-split ----------------
__global__ void k_wsplit(const float* __restrict__ W1, const float* __restrict__ W2,
                         const float* __restrict__ Wh1, const float* __restrict__ emb) {
    int i = blockIdx.x * blockDim.x + threadIdx.x;
    float v; __nv_bfloat16* dh; __nv_bfloat16* dl; int o;
    if (i < W1SZ) {
        int l = i / (HD * HD), rem = i % (HD * HD);
        int row = rem / HD, col = rem % HD;
        v = W1[(size_t)l * HD * KE + (size_t)row * KE + col];
        dh = g_w1hi; dl = g_w1lo; o = i;
    } else if (i < W1SZ + W2SZ) {
        o = i - W1SZ;
        v = W2[o];
        dh = g_w2hi; dl = g_w2lo;
    } else if (i < W1SZ + W2SZ + WHSZ) {
        o = i - W1SZ - W2SZ;
        v = Wh1[o];
        dh = g_whhi; dl = g_whlo;
    } else if (i < W1SZ + W2SZ + WHSZ + EMBSZ) {
        o = i - W1SZ - W2SZ - WHSZ;
        v = emb[o];
        dh = g_ehi; dl = g_elo;
    } else return;
    __nv_bfloat16 h = __float2bfloat16_rn(v);
    dh[o] = h;
    dl[o] = __float2bfloat16_rn(v - __bfloat162float(h));
}

// ---------------- warp-MMA helpers ----------------
__device__ __forceinline__ uint32_t s2u(const void* p) {
    return (uint32_t)__cvta_generic_to_shared(p);
}
__device__ __forceinline__ void ldsm4(uint32_t* r, uint32_t addr) {
    asm volatile("ldmatrix.sync.aligned.m8n8.x4.shared.b16 {%0,%1,%2,%3}, [%4];"
        : "=r"(r[0]), "=r"(r[1]), "=r"(r[2]), "=r"(r[3]) : "r"(addr));
}
__device__ __forceinline__ void mma16816(float* d, const uint32_t* a, const uint32_t* b) {
    asm volatile("mma.sync.aligned.m16n8k16.row.col.f32.bf16.bf16.f32 "
        "{%0,%1,%2,%3}, {%4,%5,%6,%7}, {%8,%9}, {%0,%1,%2,%3};"
        : "+f"(d[0]), "+f"(d[1]), "+f"(d[2]), "+f"(d[3])
        : "r"(a[0]), "r"(a[1]), "r"(a[2]), "r"(a[3]), "r"(b[0]), "r"(b[1]));
}
__device__ __forceinline__ void cpa16(uint32_t d, const void* s) {
    asm volatile("cp.async.ca.shared.global [%0], [%1], 16;" :: "r"(d), "l"(s));
}
#define CP_COMMIT() asm volatile("cp.async.commit_group;" ::: "memory")

// ---------------- bf16x3 MMA GEMM, 512 threads, BK=64, double-buffered ----------------
// ridx: optional row-index indirection for the A0 (kc<HD) part (29-row emb table).
// Wh2v: if non-null, HEAD mode: out[row-partial] = sum_col relu(acc+bias)*Wh2[col],
//       written to hpart[row*2 + blockIdx.y]; no other output.
#define PITCH 72
#define TSZ   18432
#define STG   73728
__global__ __launch_bounds__(512) void k_gemm_mma(
    const __nv_bfloat16* __restrict__ A0h, const __nv_bfloat16* __restrict__ A0l,
    const __nv_bfloat16* __restrict__ A1h, const __nv_bfloat16* __restrict__ A1l,
    const __nv_bfloat16* __restrict__ Bh,  const __nv_bfloat16* __restrict__ Bl,
    const float* __restrict__ bias, const int* __restrict__ ridx,
    const float* __restrict__ Wh2v, float* __restrict__ hpart,
    float* __restrict__ outf, __nv_bfloat16* __restrict__ outhi, __nv_bfloat16* __restrict__ outlo,
    int K, int ws, int M, int act)
{
    extern __shared__ char smem[];
    const uint32_t us = s2u(smem);

    const int tid  = threadIdx.x;
    const int lane = tid & 31;
    const int wid  = tid >> 5;
    const int r0   = blockIdx.x * 128;
    const int nb0  = blockIdx.y * 128;
    const int m0w  = (wid >> 2) * 32;
    const int n0w  = (wid & 3) * 32;

    float acc[2][4][4];
#pragma unroll
    for (int i = 0; i < 2; i++)
#pragma unroll
        for (int j = 0; j < 4; j++)
#pragma unroll
            for (int t = 0; t < 4; t++) acc[i][j][t] = 0.f;

    const int nch = K >> 6;
    const int lr  = tid >> 2;
    const int lcb = (tid & 3) * 8;

    auto load_chunk = [&](int ch, int stage) {
        const int kc = ch << 6;
        const __nv_bfloat16* Ah = (kc < HD) ? A0h : A1h;
        const __nv_bfloat16* Al = (kc < HD) ? A0l : A1l;
        const int acol = (kc < HD) ? kc : (kc - HD);
        const uint32_t base = us + stage * STG;
        int g = r0 + lr; if (g >= M) g = M - 1;
        if (ridx && kc < HD) g = __ldg(&ridx[g]);
#pragma unroll
        for (int gi = 0; gi < 2; gi++) {
            int c = lcb + gi * 32;
            uint32_t so = (uint32_t)(lr * PITCH + c) * 2;
            cpa16(base + so,           &Ah[(size_t)g * HD + acol + c]);
            cpa16(base + TSZ + so,     &Al[(size_t)g * HD + acol + c]);
            cpa16(base + 2 * TSZ + so, &Bh[(size_t)(nb0 + lr) * ws + kc + c]);
            cpa16(base + 3 * TSZ + so, &Bl[(size_t)(nb0 + lr) * ws + kc + c]);
        }
    };

    load_chunk(0, 0);
    CP_COMMIT();

    for (int ch = 0; ch < nch; ch++) {
        if (ch + 1 < nch) {
            load_chunk(ch + 1, (ch + 1) & 1);
            CP_COMMIT();
            asm volatile("cp.async.wait_group 1;" ::: "memory");
        } else {
            asm volatile("cp.async.wait_group 0;" ::: "memory");
        }
        __syncthreads();

        const uint32_t base = us + (ch & 1) * STG;
        const uint32_t uA = base, uAl = base + TSZ, uB = base + 2 * TSZ, uBl = base + 3 * TSZ;
#pragma unroll
        for (int ks = 0; ks < 4; ks++) {
            const int kk = ks * 16;
            uint32_t ah[2][4], al[2][4];
            {
                int ar = (lane & 7) + ((lane >> 3) & 1) * 8;
                int ac = kk + ((lane >> 4) & 1) * 8;
#pragma unroll
                for (int mf = 0; mf < 2; mf++) {
                    uint32_t off = (uint32_t)((m0w + mf * 16 + ar) * PITCH + ac) * 2;
                    ldsm4(ah[mf], uA + off);
                    ldsm4(al[mf], uAl + off);
                }
            }
            uint32_t bh[2][4], bl[2][4];
            {
                int br = ((lane >> 4) & 1) * 8 + (lane & 7);
                int bc = kk + ((lane >> 3) & 1) * 8;
#pragma unroll
                for (int nb2 = 0; nb2 < 2; nb2++) {
                    uint32_t off = (uint32_t)((n0w + nb2 * 16 + br) * PITCH + bc) * 2;
                    ldsm4(bh[nb2], uB + off);
                    ldsm4(bl[nb2], uBl + off);
                }
            }
#pragma unroll
            for (int mf = 0; mf < 2; mf++)
#pragma unroll
                for (int nf = 0; nf < 4; nf++) {
                    const uint32_t* B0 = &bh[nf >> 1][(nf & 1) * 2];
                    const uint32_t* B1 = &bl[nf >> 1][(nf & 1) * 2];
                    mma16816(acc[mf][nf], ah[mf], B0);
                    mma16816(acc[mf][nf], al[mf], B0);
                    mma16816(acc[mf][nf], ah[mf], B1);
                }
        }
        __syncthreads();
    }

    const int rq = lane >> 2, cq = (lane & 3) * 2;

    if (Wh2v) {
        // ---- fused MLP head: partial[row] = sum_col relu(acc+bh1[col]) * Wh2[col] ----
        float rs[2][2] = {{0.f, 0.f}, {0.f, 0.f}};   // [mf][half]
#pragma unroll
        for (int mf = 0; mf < 2; mf++) {
#pragma unroll
            for (int nf = 0; nf < 4; nf++) {
                int col = nb0 + n0w + nf * 8 + cq;
                float b0 = __ldg(&bias[col]),  b1 = __ldg(&bias[col + 1]);
                float w0 = __ldg(&Wh2v[col]),  w1 = __ldg(&Wh2v[col + 1]);
#pragma unroll
                for (int half = 0; half < 2; half++) {
                    float ox = fmaxf(acc[mf][nf][half * 2 + 0] + b0, 0.f);
                    float oy = fmaxf(acc[mf][nf][half * 2 + 1] + b1, 0.f);
                    rs[mf][half] += ox * w0 + oy * w1;
                }
            }
        }
        // reduce over the 4 cq-lanes (same rq) — fixed order, deterministic
#pragma unroll
        for (int mf = 0; mf < 2; mf++)
#pragma unroll
            for (int half = 0; half < 2; half++) {
                rs[mf][half] += __shfl_xor_sync(0xffffffffu, rs[mf][half], 1);
                rs[mf][half] += __shfl_xor_sync(0xffffffffu, rs[mf][half], 2);
            }
        float* sp = (float*)smem;   // 128 rows x 4 n-warps
        __syncthreads();
        if ((lane & 3) == 0) {
#pragma unroll
            for (int mf = 0; mf < 2; mf++)
#pragma unroll
                for (int half = 0; half < 2; half++) {
                    int lrow = m0w + mf * 16 + rq + half * 8;
                    sp[lrow * 4 + (wid & 3)] = rs[mf][half];
                }
        }
        __syncthreads();
        if (tid < 128) {
            int grow = r0 + tid;
            if (grow < M) {
                float s = ((sp[tid * 4 + 0] + sp[tid * 4 + 1]) + sp[tid * 4 + 2]) + sp[tid * 4 + 3];
                hpart[(size_t)grow * 2 + blockIdx.y] = s;
            }
        }
        return;
    }

    // ---- normal epilogue ----
#pragma unroll
    for (int mf = 0; mf < 2; mf++) {
#pragma unroll
        for (int nf = 0; nf < 4; nf++) {
            int col = nb0 + n0w + nf * 8 + cq;
            float b0 = 0.f, b1 = 0.f;
            if (bias) { b0 = __ldg(&bias[col]); b1 = __ldg(&bias[col + 1]); }
            int row0 = r0 + m0w + mf * 16 + rq;
#pragma unroll
            for (int half = 0; half < 2; half++) {
                int row = row0 + half * 8;
                if (row < M) {
                    float ox = acc[mf][nf][half * 2 + 0] + b0;
                    float oy = acc[mf][nf][half * 2 + 1] + b1;
                    if (act) { ox = fmaxf(ox, 0.f); oy = fmaxf(oy, 0.f); }
                    size_t idx = (size_t)row * HD + col;
                    if (outf) *(float2*)&outf[idx] = make_float2(ox, oy);
                    if (outhi) {
                        __nv_bfloat16 h0 = __float2bfloat16_rn(ox);
                        __nv_bfloat16 h1 = __float2bfloat16_rn(oy);
                        *(__nv_bfloat162*)&outhi[idx] = {h0, h1};
                        *(__nv_bfloat162*)&outlo[idx] =
                            {__float2bfloat16_rn(ox - __bfloat162float(h0)),
                             __float2bfloat16_rn(oy - __bfloat162float(h1))};
                    }
                }
            }
        }
    }
}

// ---------------- fused edge + segmented mean: warp-per-node, 2-edge pipelined ----------------
#define ESEG_BLOCKS 1563
__global__ __launch_bounds__(256) void k_edge_seg(
    const float* __restrict__ z, const int* __restrict__ src,
    const float* __restrict__ w, const float* __restrict__ W1l,
    const int* __restrict__ gate0, int n)
{
    __shared__ float sc[3][HD];
    const int tid  = threadIdx.x;
    const int lane = tid & 31;
    const int wloc = tid >> 5;

    if (tid < HD) {
        sc[0][tid] = W1l[(size_t)tid * KE + HD + 0];
        sc[1][tid] = W1l[(size_t)tid * KE + HD + 1];
        sc[2][tid] = W1l[(size_t)tid * KE + HD + 2];
    }
    __syncthreads();

    const int f0 = lane * 8;
    float c0[8], c1[8], c2[8];
#pragma unroll
    for (int j = 0; j < 8; j++) {
        c0[j] = sc[0][f0 + j];
        c1[j] = sc[1][f0 + j];
        c2[j] = sc[2][f0 + j];
    }

    const int gwarp  = blockIdx.x * 8 + wloc;
    const int nwarps = ESEG_BLOCKS * 8;

    for (int v = gwarp; v < n; v += nwarps) {
        const int lo = g_rowptr[v], hi = g_rowptr[v + 1];
        float a[8];
#pragma unroll
        for (int j = 0; j < 8; j++) a[j] = 0.f;

        int i = lo;
        for (; i + 2 <= hi; i += 2) {
            int e0 = __ldg(&g_esorted[i]);
            int e1 = __ldg(&g_esorted[i + 1]);
            int s0 = __ldg(&src[e0]);
            int s1 = __ldg(&src[e1]);
            if (gate0) { s0 = __ldg(&gate0[s0]); s1 = __ldg(&gate0[s1]); }
            float w00 = __ldg(&w[(size_t)e0 * 3 + 0]);
            float w01 = __ldg(&w[(size_t)e0 * 3 + 1]);
            float w02 = __ldg(&w[(size_t)e0 * 3 + 2]);
            float w10 = __ldg(&w[(size_t)e1 * 3 + 0]);
            float w11 = __ldg(&w[(size_t)e1 * 3 + 1]);
            float w12 = __ldg(&w[(size_t)e1 * 3 + 2]);
            const float4* zr0 = (const float4*)&z[(size_t)s0 * HD];
            const float4* zr1 = (const float4*)&z[(size_t)s1 * HD];
            float4 za0 = __ldg(&zr0[lane * 2 + 0]);
            float4 zb0 = __ldg(&zr0[lane * 2 + 1]);
            float4 za1 = __ldg(&zr1[lane * 2 + 0]);
            float4 zb1 = __ldg(&zr1[lane * 2 + 1]);
            float t0[8] = {za0.x, za0.y, za0.z, za0.w, zb0.x, zb0.y, zb0.z, zb0.w};
            float t1[8] = {za1.x, za1.y, za1.z, za1.w, zb1.x, zb1.y, zb1.z, zb1.w};
#pragma unroll
            for (int j = 0; j < 8; j++) {
                float v0 = t0[j] + c0[j] * w00 + c1[j] * w01 + c2[j] * w02;
                a[j] += (v0 > 0.f) ? v0 : 0.01f * v0;
            }
#pragma unroll
            for (int j = 0; j < 8; j++) {
                float v1 = t1[j] + c0[j] * w10 + c1[j] * w11 + c2[j] * w12;
                a[j] += (v1 > 0.f) ? v1 : 0.01f * v1;
            }
        }
        if (i < hi) {
            int e = __ldg(&g_esorted[i]);
            int s = __ldg(&src[e]);
            if (gate0) s = __ldg(&gate0[s]);
            float w0 = __ldg(&w[(size_t)e * 3 + 0]);
            float w1 = __ldg(&w[(size_t)e * 3 + 1]);
            float w2 = __ldg(&w[(size_t)e * 3 + 2]);
            const float4* zr = (const float4*)&z[(size_t)s * HD];
            float4 za = __ldg(&zr[lane * 2 + 0]);
            float4 zb = __ldg(&zr[lane * 2 + 1]);
            float t[8] = {za.x, za.y, za.z, za.w, zb.x, zb.y, zb.z, zb.w};
#pragma unroll
            for (int j = 0; j < 8; j++) {
                float val = t[j] + c0[j] * w0 + c1[j] * w1 + c2[j] * w2;
                a[j] += (val > 0.f) ? val : 0.01f * val;
            }
        }
        const float inv = g_inv[v];
        uint32_t hpack[4], lpack[4];
#pragma unroll
        for (int j = 0; j < 4; j++) {
            float r0v = a[j * 2 + 0] * inv;
            float r1v = a[j * 2 + 1] * inv;
            __nv_bfloat16 h0 = __float2bfloat16_rn(r0v);
            __nv_bfloat16 h1 = __float2bfloat16_rn(r1v);
            __nv_bfloat162 hp = {h0, h1};
            __nv_bfloat162 lp = {__float2bfloat16_rn(r0v - __bfloat162float(h0)),
                                 __float2bfloat16_rn(r1v - __bfloat162float(h1))};
            hpack[j] = *(uint32_t*)&hp;
            lpack[j] = *(uint32_t*)&lp;
        }
        size_t idx = (size_t)v * HD + f0;
        *(uint4*)&g_nhi[idx] = *(uint4*)hpack;
        *(uint4*)&g_nlo[idx] = *(uint4*)lpack;
    }
}

// ---------------- head partial combine ----------------
__global__ void k_headsum(const float* __restrict__ bh2, float* __restrict__ out, int n) {
    int v = blockIdx.x * blockDim.x + threadIdx.x;
    if (v >= n) return;
    out[v] = g_part[(size_t)v * 2 + 0] + g_part[(size_t)v * 2 + 1] + bh2[0];
}

// ---------------- host ----------------
extern "C" void kernel_launch(void* const* d_in, const int* in_sizes, int n_in,
                              void* d_out, int out_size) {
    const int*   gate = (const int*)  d_in[0];
    const int*   src  = (const int*)  d_in[1];
    const int*   dst  = (const int*)  d_in[2];
    const float* w    = (const float*)d_in[3];
    const float* emb  = (const float*)d_in[4];
    const float* W1   = (const float*)d_in[5];
    const float* W2   = (const float*)d_in[6];
    const float* b2   = (const float*)d_in[7];
    const float* Wh1  = (const float*)d_in[8];
    const float* bh1  = (const float*)d_in[9];
    const float* Wh2  = (const float*)d_in[10];
    const float* bh2  = (const float*)d_in[11];
    float* out = (float*)d_out;

    int n = in_sizes[0];
    int e = in_sizes[1];

    static cudaStream_t s2 = nullptr;
    static cudaEvent_t evFork = nullptr, evCSR = nullptr;
    if (!s2) {   // first call = uncaptured correctness run
        cudaFuncSetAttribute(k_gemm_mma, cudaFuncAttributeMaxDynamicSharedMemorySize, 2 * STG);
        cudaStreamCreateWithFlags(&s2, cudaStreamNonBlocking);
        cudaEventCreateWithFlags(&evFork, cudaEventDisableTiming);
        cudaEventCreateWithFlags(&evCSR, cudaEventDisableTiming);
    }

    void* p;
    cudaGetSymbolAddress(&p, g_ahi); __nv_bfloat16* ahi = (__nv_bfloat16*)p;
    cudaGetSymbolAddress(&p, g_alo); __nv_bfloat16* alo = (__nv_bfloat16*)p;
    cudaGetSymbolAddress(&p, g_bhi); __nv_bfloat16* bhi = (__nv_bfloat16*)p;
    cudaGetSymbolAddress(&p, g_blo); __nv_bfloat16* blo = (__nv_bfloat16*)p;
    cudaGetSymbolAddress(&p, g_nhi); __nv_bfloat16* nhi = (__nv_bfloat16*)p;
    cudaGetSymbolAddress(&p, g_nlo); __nv_bfloat16* nlo = (__nv_bfloat16*)p;
    cudaGetSymbolAddress(&p, g_z);   float* z = (float*)p;
    cudaGetSymbolAddress(&p, g_zem); float* zem = (float*)p;
    cudaGetSymbolAddress(&p, g_part); float* part = (float*)p;
    cudaGetSymbolAddress(&p, g_w1hi); __nv_bfloat16* w1hi = (__nv_bfloat16*)p;
    cudaGetSymbolAddress(&p, g_w1lo); __nv_bfloat16* w1lo = (__nv_bfloat16*)p;
    cudaGetSymbolAddress(&p, g_w2hi); __nv_bfloat16* w2hi = (__nv_bfloat16*)p;
    cudaGetSymbolAddress(&p, g_w2lo); __nv_bfloat16* w2lo = (__nv_bfloat16*)p;
    cudaGetSymbolAddress(&p, g_whhi); __nv_bfloat16* whhi = (__nv_bfloat16*)p;
    cudaGetSymbolAddress(&p, g_whlo); __nv_bfloat16* whlo = (__nv_bfloat16*)p;
    cudaGetSymbolAddress(&p, g_ehi); __nv_bfloat16* ehi = (__nv_bfloat16*)p;
    cudaGetSymbolAddress(&p, g_elo); __nv_bfloat16* elo = (__nv_bfloat16*)p;

    // ---- fork s2 FROM the capture-origin stream (required for graph capture) ----
    cudaEventRecord(evFork, 0);
    cudaStreamWaitEvent(s2, evFork, 0);

    // ---- CSR prep on s2 (only needed at the first edge_seg) ----
    k_zero_deg<<<(n + 255) / 256, 256, 0, s2>>>(n);
    k_deg     <<<(e + 255) / 256, 256, 0, s2>>>(dst, e);
    k_scan    <<<1, 1024, 0, s2>>>(n);
    k_scatter <<<(e + 255) / 256, 256, 0, s2>>>(dst, e);
    k_segsort <<<(n + 255) / 256, 256, 0, s2>>>(n);
    cudaEventRecord(evCSR, s2);

    // ---- weight/emb prep + zem on main stream (concurrent with CSR) ----
    k_wsplit <<<(W1SZ + W2SZ + WHSZ + EMBSZ + 255) / 256, 256>>>(W1, W2, Wh1, emb);

    __nv_bfloat16 *pah = ahi, *pal = alo, *pbh = bhi, *pbl = blo;
    dim3 gg((n + 127) / 128, 2);
    dim3 gt(1, 2);

    // zem = emb @ W1_0^T  (29-row GEMM; bit-identical rows to per-node z0)
    k_gemm_mma<<<gt, 512, 2 * STG>>>(ehi, elo, ehi, elo, w1hi, w1lo,
                                     nullptr, nullptr, nullptr, nullptr,
                                     zem, nullptr, nullptr, HD, HD, NGT, 0);

    // join: CSR must be ready before first edge_seg
    cudaStreamWaitEvent(0, evCSR, 0);

    for (int l = 0; l < NL; l++) {
        const float* W1l = W1 + (size_t)l * HD * KE;
        if (l > 0) {
            k_gemm_mma<<<gg, 512, 2 * STG>>>(pah, pal, pah, pal,
                                             w1hi + (size_t)l * HD * HD, w1lo + (size_t)l * HD * HD,
                                             nullptr, nullptr, nullptr, nullptr,
                                             z, nullptr, nullptr, HD, HD, n, 0);
            k_edge_seg<<<ESEG_BLOCKS, 256>>>(z, src, w, W1l, nullptr, n);
            k_gemm_mma<<<gg, 512, 2 * STG>>>(pah, pal, nhi, nlo,
                                             w2hi + (size_t)l * HD * 512, w2lo + (size_t)l * HD * 512,
                                             b2 + (size_t)l * HD, nullptr, nullptr, nullptr,
                                             nullptr, pbh, pbl, 512, 512, n, 1);
        } else {
            // layer 0: z rows come from the 29-row zem table (gate-indirect)
            k_edge_seg<<<ESEG_BLOCKS, 256>>>(zem, src, w, W1l, gate, n);
            // node GEMM: A0 = emb tables gathered through gate (L1-resident)
            k_gemm_mma<<<gg, 512, 2 * STG>>>(ehi, elo, nhi, nlo,
                                             w2hi, w2lo,
                                             b2, gate, nullptr, nullptr,
                                             nullptr, pbh, pbl, 512, 512, n, 1);
        }
        __nv_bfloat16* t;
        t = pah; pah = pbh; pbh = t;
        t = pal; pal = pbl; pbl = t;
    }
    // fused MLP head: partial dot with Wh2 inside the GEMM epilogue
    k_gemm_mma<<<gg, 512, 2 * STG>>>(pah, pal, pah, pal, whhi, whlo,
                                     bh1, nullptr, Wh2, part,
                                     nullptr, nullptr, nullptr, HD, HD, n, 1);
    k_headsum<<<(n + 255) / 256, 256>>>(bh2, out, n);
}